// round 3
// baseline (speedup 1.0000x reference)
#include <cuda_runtime.h>
#include <cuda_bf16.h>
#include <math.h>

// ---------------- problem constants ----------------
#define BB 2
#define SS 2048
#define HH 2304
#define NH 8
#define NKV 4
#define HD 256
#define FF 9216
#define MROWS (BB * SS)          // 4096
#define QC (NH * HD)             // 2048
#define KC (NKV * HD)            // 1024
#define SOFTCAP 50.0f
#define ATT_SCALE 0.0625f        // 256^-0.5
#define RMS_EPS 1e-6f

// ---------------- scratch (device globals; no allocations) ----------------
__device__ float g_h   [(size_t)MROWS * HH];
__device__ float g_q   [(size_t)MROWS * QC];
__device__ float g_k   [(size_t)MROWS * KC];
__device__ float g_v   [(size_t)MROWS * KC];
__device__ float g_sc  [(size_t)BB * NH * SS * SS];   // 256 MB
__device__ float g_o   [(size_t)MROWS * QC];
__device__ float g_attn[(size_t)MROWS * HH];
__device__ float g_h2  [(size_t)MROWS * HH];
__device__ float g_f   [(size_t)MROWS * HH];
__device__ float g_gate[(size_t)MROWS * FF];
__device__ float g_up  [(size_t)MROWS * FF];
__device__ float g_mlp [(size_t)MROWS * HH];

// ---------------- generic tiled GEMM body ----------------
// C[m,n] = sum_k A[m,k] * B(k,n)   (TB=false: B row-major [K,N]; TB=true: B is [N,K], i.e. A@B^T)
// Tiles: 128x128xK16, 256 threads, 8x8 per thread. Grid: (N/128, M/128).
template<bool TB>
__device__ __forceinline__ void gemm_body(const float* __restrict__ A,
                                          const float* __restrict__ Bm,
                                          float* __restrict__ C,
                                          int K, int lda, int ldb, int ldc) {
    __shared__ float As[16][128];
    __shared__ float Bs[16][128];

    const int m0 = blockIdx.y * 128;
    const int n0 = blockIdx.x * 128;
    const int tid = threadIdx.x;
    const int tx = tid & 15;        // 0..15 -> 8 cols each
    const int ty = tid >> 4;        // 0..15 -> 8 rows each

    float acc[8][8];
#pragma unroll
    for (int i = 0; i < 8; i++)
#pragma unroll
        for (int j = 0; j < 8; j++) acc[i][j] = 0.0f;

    for (int k0 = 0; k0 < K; k0 += 16) {
        // load A tile (128 rows x 16 k), store transposed As[k][m]
#pragma unroll
        for (int i = 0; i < 8; i++) {
            int flat = i * 256 + tid;
            int r = flat >> 4, c = flat & 15;
            As[c][r] = A[(size_t)(m0 + r) * lda + (k0 + c)];
        }
        // load B tile
#pragma unroll
        for (int i = 0; i < 8; i++) {
            int flat = i * 256 + tid;
            if (TB) {
                int r = flat >> 4, c = flat & 15;   // r = n index, c = k index
                Bs[c][r] = Bm[(size_t)(n0 + r) * ldb + (k0 + c)];
            } else {
                int r = flat >> 7, c = flat & 127;  // r = k index, c = n index
                Bs[r][c] = Bm[(size_t)(k0 + r) * ldb + (n0 + c)];
            }
        }
        __syncthreads();

#pragma unroll
        for (int kk = 0; kk < 16; kk++) {
            float a[8], b[8];
#pragma unroll
            for (int i = 0; i < 8; i++) a[i] = As[kk][ty * 8 + i];
#pragma unroll
            for (int j = 0; j < 8; j++) b[j] = Bs[kk][tx * 8 + j];
#pragma unroll
            for (int i = 0; i < 8; i++)
#pragma unroll
                for (int j = 0; j < 8; j++)
                    acc[i][j] = fmaf(a[i], b[j], acc[i][j]);
        }
        __syncthreads();
    }

#pragma unroll
    for (int i = 0; i < 8; i++) {
        float* crow = C + (size_t)(m0 + ty * 8 + i) * ldc + n0 + tx * 8;
#pragma unroll
        for (int j = 0; j < 8; j++) crow[j] = acc[i][j];
    }
}

__global__ void __launch_bounds__(256) k_gemm_nn(const float* __restrict__ A,
                                                 const float* __restrict__ Bm,
                                                 float* __restrict__ C,
                                                 int K, int lda, int ldb, int ldc) {
    gemm_body<false>(A, Bm, C, K, lda, ldb, ldc);
}

// batched QK^T: scores[bh, qi, kj] = q[b,qi,h,:]·k[b,kj,h/2,:]
__global__ void __launch_bounds__(256) k_qk() {
    int bh = blockIdx.z;
    int b = bh >> 3, h = bh & 7;
    const float* A  = g_q + (size_t)b * SS * QC + h * HD;
    const float* Bm = g_k + (size_t)b * SS * KC + (h >> 1) * HD;
    float* C = g_sc + (size_t)bh * SS * SS;
    gemm_body<true>(A, Bm, C, HD, QC, KC, SS);
}

// batched PV: o[b,qi,h,:] = sum_k p[bh,qi,k] * v[b,k,h/2,:]
__global__ void __launch_bounds__(256) k_pv() {
    int bh = blockIdx.z;
    int b = bh >> 3, h = bh & 7;
    const float* A  = g_sc + (size_t)bh * SS * SS;
    const float* Bm = g_v + (size_t)b * SS * KC + (h >> 1) * HD;
    float* C = g_o + (size_t)b * SS * QC + h * HD;
    gemm_body<false>(A, Bm, C, SS, SS, KC, QC);
}

// ---------------- rmsnorm family ----------------
__global__ void __launch_bounds__(256) k_rmsnorm(const float* __restrict__ x,
                                                 const float* __restrict__ g,
                                                 float* __restrict__ out) {
    int row = blockIdx.x;
    const float* xr = x + (size_t)row * HH;
    float s = 0.0f;
    for (int i = threadIdx.x; i < HH; i += 256) { float v = xr[i]; s = fmaf(v, v, s); }
    __shared__ float red[256];
    red[threadIdx.x] = s;
    __syncthreads();
    for (int off = 128; off > 0; off >>= 1) {
        if (threadIdx.x < off) red[threadIdx.x] += red[threadIdx.x + off];
        __syncthreads();
    }
    float rstd = rsqrtf(red[0] * (1.0f / HH) + RMS_EPS);
    float* orow = out + (size_t)row * HH;
    for (int i = threadIdx.x; i < HH; i += 256)
        orow[i] = xr[i] * rstd * (1.0f + g[i]);
}

// out = res + rmsnorm(y, g)
__global__ void __launch_bounds__(256) k_add_rms(const float* __restrict__ res,
                                                 const float* __restrict__ y,
                                                 const float* __restrict__ g,
                                                 float* __restrict__ out) {
    int row = blockIdx.x;
    const float* yr = y + (size_t)row * HH;
    float s = 0.0f;
    for (int i = threadIdx.x; i < HH; i += 256) { float v = yr[i]; s = fmaf(v, v, s); }
    __shared__ float red[256];
    red[threadIdx.x] = s;
    __syncthreads();
    for (int off = 128; off > 0; off >>= 1) {
        if (threadIdx.x < off) red[threadIdx.x] += red[threadIdx.x + off];
        __syncthreads();
    }
    float rstd = rsqrtf(red[0] * (1.0f / HH) + RMS_EPS);
    const float* rr = res + (size_t)row * HH;
    float* orow = out + (size_t)row * HH;
    for (int i = threadIdx.x; i < HH; i += 256)
        orow[i] = rr[i] + yr[i] * rstd * (1.0f + g[i]);
}

// ---------------- RoPE ----------------
// heads 0..7 = q heads, 8..11 = k heads; pair (j, j+128) per thread
__global__ void __launch_bounds__(256) k_rope() {
    int idx = blockIdx.x * 256 + threadIdx.x;            // < 4096*12*128
    int j = idx & 127;
    int hd = (idx >> 7) % 12;
    int row = idx / (12 * 128);
    int pos = row & (SS - 1);
    float inv = __powf(10000.0f, -(float)(2 * j) * (1.0f / HD));
    float fr = (float)pos * inv;
    float sn, cs;
    sincosf(fr, &sn, &cs);
    float* base = (hd < 8) ? (g_q + (size_t)row * QC + hd * HD)
                           : (g_k + (size_t)row * KC + (hd - 8) * HD);
    float v0 = base[j], v1 = base[j + 128];
    base[j]       = v0 * cs - v1 * sn;
    base[j + 128] = v1 * cs + v0 * sn;
}

// ---------------- softmax with softcap + causal mask ----------------
__global__ void __launch_bounds__(256) k_softmax() {
    int r = blockIdx.x;                 // bh*SS + qi
    int qi = r & (SS - 1);
    float* row = g_sc + (size_t)r * SS;
    int t = threadIdx.x;
    float vals[8];
    float mx = -1e30f;
#pragma unroll
    for (int i = 0; i < 8; i++) {
        int j = t + i * 256;
        float s = row[j] * ATT_SCALE;
        s = SOFTCAP * tanhf(s * (1.0f / SOFTCAP));
        if (j > qi) s -= 1e9f;
        vals[i] = s;
        mx = fmaxf(mx, s);
    }
    __shared__ float red[256];
    red[t] = mx;
    __syncthreads();
    for (int off = 128; off > 0; off >>= 1) {
        if (t < off) red[t] = fmaxf(red[t], red[t + off]);
        __syncthreads();
    }
    mx = red[0];
    __syncthreads();
    float sum = 0.0f;
#pragma unroll
    for (int i = 0; i < 8; i++) { vals[i] = __expf(vals[i] - mx); sum += vals[i]; }
    red[t] = sum;
    __syncthreads();
    for (int off = 128; off > 0; off >>= 1) {
        if (t < off) red[t] += red[t + off];
        __syncthreads();
    }
    float inv = 1.0f / red[0];
#pragma unroll
    for (int i = 0; i < 8; i++) row[t + i * 256] = vals[i] * inv;
}

// ---------------- GeGLU (tanh-approx gelu) ----------------
__global__ void __launch_bounds__(256) k_geglu() {
    int i = blockIdx.x * 256 + threadIdx.x;              // < 4096*9216
    float x = g_gate[i];
    float u = g_up[i];
    const float c0 = 0.7978845608028654f;                // sqrt(2/pi)
    float inner = c0 * fmaf(0.044715f * x * x, x, x);
    float tgt = tanhf(inner);
    g_gate[i] = 0.5f * x * (1.0f + tgt) * u;
}

// ---------------- launch ----------------
extern "C" void kernel_launch(void* const* d_in, const int* in_sizes, int n_in,
                              void* d_out, int out_size) {
    const float* x         = (const float*)d_in[0];
    // d_in[1] = mask (pure causal; applied analytically in k_softmax)
    const float* wq        = (const float*)d_in[2];
    const float* wk        = (const float*)d_in[3];
    const float* wv        = (const float*)d_in[4];
    const float* wo        = (const float*)d_in[5];
    const float* w_gate    = (const float*)d_in[6];
    const float* w_up      = (const float*)d_in[7];
    const float* w_down    = (const float*)d_in[8];
    const float* gin       = (const float*)d_in[9];
    const float* gpa       = (const float*)d_in[10];
    const float* gpf       = (const float*)d_in[11];
    const float* gpff      = (const float*)d_in[12];
    float* out = (float*)d_out;

    float *p_h, *p_q, *p_k, *p_v, *p_o, *p_attn, *p_h2, *p_f, *p_gate, *p_up, *p_mlp;
    cudaGetSymbolAddress((void**)&p_h,    g_h);
    cudaGetSymbolAddress((void**)&p_q,    g_q);
    cudaGetSymbolAddress((void**)&p_k,    g_k);
    cudaGetSymbolAddress((void**)&p_v,    g_v);
    cudaGetSymbolAddress((void**)&p_o,    g_o);
    cudaGetSymbolAddress((void**)&p_attn, g_attn);
    cudaGetSymbolAddress((void**)&p_h2,   g_h2);
    cudaGetSymbolAddress((void**)&p_f,    g_f);
    cudaGetSymbolAddress((void**)&p_gate, g_gate);
    cudaGetSymbolAddress((void**)&p_up,   g_up);
    cudaGetSymbolAddress((void**)&p_mlp,  g_mlp);

    // 1. h = rmsnorm(x, g_in)
    k_rmsnorm<<<MROWS, 256>>>(x, gin, p_h);

    // 2-4. q/k/v projections
    k_gemm_nn<<<dim3(QC / 128, MROWS / 128), 256>>>(p_h, wq, p_q, HH, HH, QC, QC);
    k_gemm_nn<<<dim3(KC / 128, MROWS / 128), 256>>>(p_h, wk, p_k, HH, HH, KC, KC);
    k_gemm_nn<<<dim3(KC / 128, MROWS / 128), 256>>>(p_h, wv, p_v, HH, HH, KC, KC);

    // 5. RoPE on q and k
    k_rope<<<(MROWS * 12 * 128) / 256, 256>>>();

    // 6. scores = q @ k^T (batched over b,h)
    k_qk<<<dim3(SS / 128, SS / 128, BB * NH), 256>>>();

    // 7. softcap + causal mask + softmax
    k_softmax<<<BB * NH * SS, 256>>>();

    // 8. o = p @ v (batched, writes [B,S,NH,HD] layout directly)
    k_pv<<<dim3(HD / 128, SS / 128, BB * NH), 256>>>();

    // 9. attn_out = o @ wo
    k_gemm_nn<<<dim3(HH / 128, MROWS / 128), 256>>>(p_o, wo, p_attn, QC, QC, HH, HH);

    // 10. h2 = x + rmsnorm(attn_out, g_post_attn)
    k_add_rms<<<MROWS, 256>>>(x, p_attn, gpa, p_h2);

    // 11. f = rmsnorm(h2, g_pre_ff)
    k_rmsnorm<<<MROWS, 256>>>(p_h2, gpf, p_f);

    // 12-13. gate/up projections
    k_gemm_nn<<<dim3(FF / 128, MROWS / 128), 256>>>(p_f, w_gate, p_gate, HH, HH, FF, FF);
    k_gemm_nn<<<dim3(FF / 128, MROWS / 128), 256>>>(p_f, w_up,   p_up,   HH, HH, FF, FF);

    // 14. gate = gelu_tanh(gate) * up
    k_geglu<<<(MROWS * FF) / 256, 256>>>();

    // 15. mlp = act @ w_down
    k_gemm_nn<<<dim3(HH / 128, MROWS / 128), 256>>>(p_gate, w_down, p_mlp, FF, FF, HH, HH);

    // 16. out = h2 + rmsnorm(mlp, g_post_ff)
    k_add_rms<<<MROWS, 256>>>(p_h2, p_mlp, gpff, out);
}

// round 4
// speedup vs baseline: 1.0006x; 1.0006x over previous
#include <cuda_runtime.h>
#include <cuda_bf16.h>
#include <math.h>

// ---------------- problem constants ----------------
#define BB 2
#define SS 2048
#define HH 2304
#define NH 8
#define NKV 4
#define HD 256
#define FF 9216
#define MROWS (BB * SS)          // 4096
#define QC (NH * HD)             // 2048
#define KC (NKV * HD)            // 1024
#define SOFTCAP 50.0f
#define ATT_SCALE 0.0625f        // 256^-0.5
#define RMS_EPS 1e-6f

// ---------------- scratch (device globals; no allocations) ----------------
__device__ float g_h   [(size_t)MROWS * HH];
__device__ float g_q   [(size_t)MROWS * QC];
__device__ float g_k   [(size_t)MROWS * KC];
__device__ float g_v   [(size_t)MROWS * KC];
__device__ float g_sc  [(size_t)BB * NH * SS * SS];   // 256 MB
__device__ float g_o   [(size_t)MROWS * QC];
__device__ float g_attn[(size_t)MROWS * HH];
__device__ float g_h2  [(size_t)MROWS * HH];
__device__ float g_f   [(size_t)MROWS * HH];
__device__ float g_gate[(size_t)MROWS * FF];
__device__ float g_up  [(size_t)MROWS * FF];
__device__ float g_mlp [(size_t)MROWS * HH];

// ---------------- generic tiled GEMM body ----------------
// C[m,n] = sum_k A[m,k] * B(k,n)   (TB=false: B row-major [K,N]; TB=true: B is [N,K], i.e. A@B^T)
// Tiles: 128x128xK16, 256 threads, 8x8 per thread. Grid: (N/128, M/128).
template<bool TB>
__device__ __forceinline__ void gemm_body(const float* __restrict__ A,
                                          const float* __restrict__ Bm,
                                          float* __restrict__ C,
                                          int K, int lda, int ldb, int ldc) {
    __shared__ float As[16][128];
    __shared__ float Bs[16][128];

    const int m0 = blockIdx.y * 128;
    const int n0 = blockIdx.x * 128;
    const int tid = threadIdx.x;
    const int tx = tid & 15;        // 0..15 -> 8 cols each
    const int ty = tid >> 4;        // 0..15 -> 8 rows each

    float acc[8][8];
#pragma unroll
    for (int i = 0; i < 8; i++)
#pragma unroll
        for (int j = 0; j < 8; j++) acc[i][j] = 0.0f;

    for (int k0 = 0; k0 < K; k0 += 16) {
        // load A tile (128 rows x 16 k), store transposed As[k][m]
#pragma unroll
        for (int i = 0; i < 8; i++) {
            int flat = i * 256 + tid;
            int r = flat >> 4, c = flat & 15;
            As[c][r] = A[(size_t)(m0 + r) * lda + (k0 + c)];
        }
        // load B tile
#pragma unroll
        for (int i = 0; i < 8; i++) {
            int flat = i * 256 + tid;
            if (TB) {
                int r = flat >> 4, c = flat & 15;   // r = n index, c = k index
                Bs[c][r] = Bm[(size_t)(n0 + r) * ldb + (k0 + c)];
            } else {
                int r = flat >> 7, c = flat & 127;  // r = k index, c = n index
                Bs[r][c] = Bm[(size_t)(k0 + r) * ldb + (n0 + c)];
            }
        }
        __syncthreads();

#pragma unroll
        for (int kk = 0; kk < 16; kk++) {
            float a[8], b[8];
#pragma unroll
            for (int i = 0; i < 8; i++) a[i] = As[kk][ty * 8 + i];
#pragma unroll
            for (int j = 0; j < 8; j++) b[j] = Bs[kk][tx * 8 + j];
#pragma unroll
            for (int i = 0; i < 8; i++)
#pragma unroll
                for (int j = 0; j < 8; j++)
                    acc[i][j] = fmaf(a[i], b[j], acc[i][j]);
        }
        __syncthreads();
    }

#pragma unroll
    for (int i = 0; i < 8; i++) {
        float* crow = C + (size_t)(m0 + ty * 8 + i) * ldc + n0 + tx * 8;
#pragma unroll
        for (int j = 0; j < 8; j++) crow[j] = acc[i][j];
    }
}

__global__ void __launch_bounds__(256) k_gemm_nn(const float* __restrict__ A,
                                                 const float* __restrict__ Bm,
                                                 float* __restrict__ C,
                                                 int K, int lda, int ldb, int ldc) {
    gemm_body<false>(A, Bm, C, K, lda, ldb, ldc);
}

// batched QK^T: scores[bh, qi, kj] = q[b,qi,h,:]·k[b,kj,h/2,:]
__global__ void __launch_bounds__(256) k_qk() {
    int bh = blockIdx.z;
    int b = bh >> 3, h = bh & 7;
    const float* A  = g_q + (size_t)b * SS * QC + h * HD;
    const float* Bm = g_k + (size_t)b * SS * KC + (h >> 1) * HD;
    float* C = g_sc + (size_t)bh * SS * SS;
    gemm_body<true>(A, Bm, C, HD, QC, KC, SS);
}

// batched PV: o[b,qi,h,:] = sum_k p[bh,qi,k] * v[b,k,h/2,:]
__global__ void __launch_bounds__(256) k_pv() {
    int bh = blockIdx.z;
    int b = bh >> 3, h = bh & 7;
    const float* A  = g_sc + (size_t)bh * SS * SS;
    const float* Bm = g_v + (size_t)b * SS * KC + (h >> 1) * HD;
    float* C = g_o + (size_t)b * SS * QC + h * HD;
    gemm_body<false>(A, Bm, C, SS, SS, KC, QC);
}

// ---------------- rmsnorm family ----------------
__global__ void __launch_bounds__(256) k_rmsnorm(const float* __restrict__ x,
                                                 const float* __restrict__ g,
                                                 float* __restrict__ out) {
    int row = blockIdx.x;
    const float* xr = x + (size_t)row * HH;
    float s = 0.0f;
    for (int i = threadIdx.x; i < HH; i += 256) { float v = xr[i]; s = fmaf(v, v, s); }
    __shared__ float red[256];
    red[threadIdx.x] = s;
    __syncthreads();
    for (int off = 128; off > 0; off >>= 1) {
        if (threadIdx.x < off) red[threadIdx.x] += red[threadIdx.x + off];
        __syncthreads();
    }
    float rstd = rsqrtf(red[0] * (1.0f / HH) + RMS_EPS);
    float* orow = out + (size_t)row * HH;
    for (int i = threadIdx.x; i < HH; i += 256)
        orow[i] = xr[i] * rstd * (1.0f + g[i]);
}

// out = res + rmsnorm(y, g)
__global__ void __launch_bounds__(256) k_add_rms(const float* __restrict__ res,
                                                 const float* __restrict__ y,
                                                 const float* __restrict__ g,
                                                 float* __restrict__ out) {
    int row = blockIdx.x;
    const float* yr = y + (size_t)row * HH;
    float s = 0.0f;
    for (int i = threadIdx.x; i < HH; i += 256) { float v = yr[i]; s = fmaf(v, v, s); }
    __shared__ float red[256];
    red[threadIdx.x] = s;
    __syncthreads();
    for (int off = 128; off > 0; off >>= 1) {
        if (threadIdx.x < off) red[threadIdx.x] += red[threadIdx.x + off];
        __syncthreads();
    }
    float rstd = rsqrtf(red[0] * (1.0f / HH) + RMS_EPS);
    const float* rr = res + (size_t)row * HH;
    float* orow = out + (size_t)row * HH;
    for (int i = threadIdx.x; i < HH; i += 256)
        orow[i] = rr[i] + yr[i] * rstd * (1.0f + g[i]);
}

// ---------------- RoPE ----------------
// heads 0..7 = q heads, 8..11 = k heads; pair (j, j+128) per thread
__global__ void __launch_bounds__(256) k_rope() {
    int idx = blockIdx.x * 256 + threadIdx.x;            // < 4096*12*128
    int j = idx & 127;
    int hd = (idx >> 7) % 12;
    int row = idx / (12 * 128);
    int pos = row & (SS - 1);
    float inv = __powf(10000.0f, -(float)(2 * j) * (1.0f / HD));
    float fr = (float)pos * inv;
    float sn, cs;
    sincosf(fr, &sn, &cs);
    float* base = (hd < 8) ? (g_q + (size_t)row * QC + hd * HD)
                           : (g_k + (size_t)row * KC + (hd - 8) * HD);
    float v0 = base[j], v1 = base[j + 128];
    base[j]       = v0 * cs - v1 * sn;
    base[j + 128] = v1 * cs + v0 * sn;
}

// ---------------- softmax with softcap + causal mask ----------------
__global__ void __launch_bounds__(256) k_softmax() {
    int r = blockIdx.x;                 // bh*SS + qi
    int qi = r & (SS - 1);
    float* row = g_sc + (size_t)r * SS;
    int t = threadIdx.x;
    float vals[8];
    float mx = -1e30f;
#pragma unroll
    for (int i = 0; i < 8; i++) {
        int j = t + i * 256;
        float s = row[j] * ATT_SCALE;
        s = SOFTCAP * tanhf(s * (1.0f / SOFTCAP));
        if (j > qi) s -= 1e9f;
        vals[i] = s;
        mx = fmaxf(mx, s);
    }
    __shared__ float red[256];
    red[t] = mx;
    __syncthreads();
    for (int off = 128; off > 0; off >>= 1) {
        if (t < off) red[t] = fmaxf(red[t], red[t + off]);
        __syncthreads();
    }
    mx = red[0];
    __syncthreads();
    float sum = 0.0f;
#pragma unroll
    for (int i = 0; i < 8; i++) { vals[i] = __expf(vals[i] - mx); sum += vals[i]; }
    red[t] = sum;
    __syncthreads();
    for (int off = 128; off > 0; off >>= 1) {
        if (t < off) red[t] += red[t + off];
        __syncthreads();
    }
    float inv = 1.0f / red[0];
#pragma unroll
    for (int i = 0; i < 8; i++) row[t + i * 256] = vals[i] * inv;
}

// ---------------- GeGLU (tanh-approx gelu) ----------------
__global__ void __launch_bounds__(256) k_geglu() {
    int i = blockIdx.x * 256 + threadIdx.x;              // < 4096*9216
    float x = g_gate[i];
    float u = g_up[i];
    const float c0 = 0.7978845608028654f;                // sqrt(2/pi)
    float inner = c0 * fmaf(0.044715f * x * x, x, x);
    float tgt = tanhf(inner);
    g_gate[i] = 0.5f * x * (1.0f + tgt) * u;
}

// ---------------- launch ----------------
extern "C" void kernel_launch(void* const* d_in, const int* in_sizes, int n_in,
                              void* d_out, int out_size) {
    const float* x         = (const float*)d_in[0];
    // d_in[1] = mask (pure causal; applied analytically in k_softmax)
    const float* wq        = (const float*)d_in[2];
    const float* wk        = (const float*)d_in[3];
    const float* wv        = (const float*)d_in[4];
    const float* wo        = (const float*)d_in[5];
    const float* w_gate    = (const float*)d_in[6];
    const float* w_up      = (const float*)d_in[7];
    const float* w_down    = (const float*)d_in[8];
    const float* gin       = (const float*)d_in[9];
    const float* gpa       = (const float*)d_in[10];
    const float* gpf       = (const float*)d_in[11];
    const float* gpff      = (const float*)d_in[12];
    float* out = (float*)d_out;

    float *p_h, *p_q, *p_k, *p_v, *p_o, *p_attn, *p_h2, *p_f, *p_gate, *p_up, *p_mlp;
    cudaGetSymbolAddress((void**)&p_h,    g_h);
    cudaGetSymbolAddress((void**)&p_q,    g_q);
    cudaGetSymbolAddress((void**)&p_k,    g_k);
    cudaGetSymbolAddress((void**)&p_v,    g_v);
    cudaGetSymbolAddress((void**)&p_o,    g_o);
    cudaGetSymbolAddress((void**)&p_attn, g_attn);
    cudaGetSymbolAddress((void**)&p_h2,   g_h2);
    cudaGetSymbolAddress((void**)&p_f,    g_f);
    cudaGetSymbolAddress((void**)&p_gate, g_gate);
    cudaGetSymbolAddress((void**)&p_up,   g_up);
    cudaGetSymbolAddress((void**)&p_mlp,  g_mlp);

    // 1. h = rmsnorm(x, g_in)
    k_rmsnorm<<<MROWS, 256>>>(x, gin, p_h);

    // 2-4. q/k/v projections
    k_gemm_nn<<<dim3(QC / 128, MROWS / 128), 256>>>(p_h, wq, p_q, HH, HH, QC, QC);
    k_gemm_nn<<<dim3(KC / 128, MROWS / 128), 256>>>(p_h, wk, p_k, HH, HH, KC, KC);
    k_gemm_nn<<<dim3(KC / 128, MROWS / 128), 256>>>(p_h, wv, p_v, HH, HH, KC, KC);

    // 5. RoPE on q and k
    k_rope<<<(MROWS * 12 * 128) / 256, 256>>>();

    // 6. scores = q @ k^T (batched over b,h)
    k_qk<<<dim3(SS / 128, SS / 128, BB * NH), 256>>>();

    // 7. softcap + causal mask + softmax
    k_softmax<<<BB * NH * SS, 256>>>();

    // 8. o = p @ v (batched, writes [B,S,NH,HD] layout directly)
    k_pv<<<dim3(HD / 128, SS / 128, BB * NH), 256>>>();

    // 9. attn_out = o @ wo
    k_gemm_nn<<<dim3(HH / 128, MROWS / 128), 256>>>(p_o, wo, p_attn, QC, QC, HH, HH);

    // 10. h2 = x + rmsnorm(attn_out, g_post_attn)
    k_add_rms<<<MROWS, 256>>>(x, p_attn, gpa, p_h2);

    // 11. f = rmsnorm(h2, g_pre_ff)
    k_rmsnorm<<<MROWS, 256>>>(p_h2, gpf, p_f);

    // 12-13. gate/up projections
    k_gemm_nn<<<dim3(FF / 128, MROWS / 128), 256>>>(p_f, w_gate, p_gate, HH, HH, FF, FF);
    k_gemm_nn<<<dim3(FF / 128, MROWS / 128), 256>>>(p_f, w_up,   p_up,   HH, HH, FF, FF);

    // 14. gate = gelu_tanh(gate) * up
    k_geglu<<<(MROWS * FF) / 256, 256>>>();

    // 15. mlp = act @ w_down
    k_gemm_nn<<<dim3(HH / 128, MROWS / 128), 256>>>(p_gate, w_down, p_mlp, FF, FF, HH, HH);

    // 16. out = h2 + rmsnorm(mlp, g_post_ff)
    k_add_rms<<<MROWS, 256>>>(p_h2, p_mlp, gpff, out);
}

// round 7
// speedup vs baseline: 3.2849x; 3.2830x over previous
#include <cuda_runtime.h>
#include <cuda_bf16.h>
#include <math.h>
#include <stdint.h>

// ---------------- problem constants ----------------
#define BB 2
#define SS 2048
#define HH 2304
#define NH 8
#define NKV 4
#define HD 256
#define FF 9216
#define MROWS (BB * SS)          // 4096
#define QC (NH * HD)             // 2048
#define KC (NKV * HD)            // 1024
#define SOFTCAP 50.0f
#define ATT_SCALE 0.0625f
#define RMS_EPS 1e-6f

typedef __nv_bfloat16 bf16;

// ---------------- scratch (device globals; no allocations) ----------------
#define DEVBUF __device__ __align__(256)
DEVBUF bf16  s_h_hi [(size_t)MROWS * HH];   DEVBUF bf16 s_h_lo [(size_t)MROWS * HH];
DEVBUF float g_q    [(size_t)MROWS * QC];
DEVBUF float g_k    [(size_t)MROWS * KC];
DEVBUF float g_v    [(size_t)MROWS * KC];
DEVBUF bf16  s_q_hi [(size_t)MROWS * QC];   DEVBUF bf16 s_q_lo [(size_t)MROWS * QC];
DEVBUF bf16  s_k_hi [(size_t)MROWS * KC];   DEVBUF bf16 s_k_lo [(size_t)MROWS * KC];
DEVBUF bf16  s_vt_hi[(size_t)MROWS * KC];   DEVBUF bf16 s_vt_lo[(size_t)MROWS * KC];
DEVBUF float g_sc   [(size_t)BB * NH * SS * SS];
DEVBUF bf16  s_p_hi [(size_t)BB * NH * SS * SS];
DEVBUF bf16  s_p_lo [(size_t)BB * NH * SS * SS];
DEVBUF float g_o    [(size_t)MROWS * QC];
DEVBUF bf16  s_o_hi [(size_t)MROWS * QC];   DEVBUF bf16 s_o_lo [(size_t)MROWS * QC];
DEVBUF float g_attn [(size_t)MROWS * HH];
DEVBUF float g_h2   [(size_t)MROWS * HH];
DEVBUF bf16  s_f_hi [(size_t)MROWS * HH];   DEVBUF bf16 s_f_lo [(size_t)MROWS * HH];
DEVBUF float g_gate [(size_t)MROWS * FF];
DEVBUF float g_up   [(size_t)MROWS * FF];
DEVBUF bf16  s_a_hi [(size_t)MROWS * FF];   DEVBUF bf16 s_a_lo [(size_t)MROWS * FF];
DEVBUF float g_mlp  [(size_t)MROWS * HH];
// transposed + split weights ([N,K] K-major, bf16 hi/lo)
DEVBUF bf16 w_qt_hi[(size_t)QC * HH]; DEVBUF bf16 w_qt_lo[(size_t)QC * HH];
DEVBUF bf16 w_kt_hi[(size_t)KC * HH]; DEVBUF bf16 w_kt_lo[(size_t)KC * HH];
DEVBUF bf16 w_vt_hi[(size_t)KC * HH]; DEVBUF bf16 w_vt_lo[(size_t)KC * HH];
DEVBUF bf16 w_ot_hi[(size_t)HH * QC]; DEVBUF bf16 w_ot_lo[(size_t)HH * QC];
DEVBUF bf16 w_gt_hi[(size_t)FF * HH]; DEVBUF bf16 w_gt_lo[(size_t)FF * HH];
DEVBUF bf16 w_ut_hi[(size_t)FF * HH]; DEVBUF bf16 w_ut_lo[(size_t)FF * HH];
DEVBUF bf16 w_dt_hi[(size_t)HH * FF]; DEVBUF bf16 w_dt_lo[(size_t)HH * FF];

// ---------------- PTX helpers (family-portable: ldmatrix / mma / cp.async) ----
__device__ __forceinline__ uint32_t smem_u32(const void* p) {
    uint32_t a;
    asm("{ .reg .u64 t; cvta.to.shared.u64 t, %1; cvt.u32.u64 %0, t; }" : "=r"(a) : "l"(p));
    return a;
}
__device__ __forceinline__ void cp16(uint32_t saddr, const void* g) {
    asm volatile("cp.async.ca.shared.global [%0], [%1], 16;" :: "r"(saddr), "l"(g));
}
#define CP_COMMIT() asm volatile("cp.async.commit_group;" ::: "memory")
#define CP_WAIT(n)  asm volatile("cp.async.wait_group %0;" :: "n"(n) : "memory")

__device__ __forceinline__ void ldsm_x4(uint32_t (&r)[4], uint32_t addr) {
    asm volatile("ldmatrix.sync.aligned.m8n8.x4.shared.b16 {%0,%1,%2,%3}, [%4];"
                 : "=r"(r[0]), "=r"(r[1]), "=r"(r[2]), "=r"(r[3]) : "r"(addr));
}
__device__ __forceinline__ void mma_bf16(float (&c)[4], const uint32_t (&a)[4],
                                         uint32_t b0, uint32_t b1) {
    asm volatile(
        "mma.sync.aligned.m16n8k16.row.col.f32.bf16.bf16.f32 "
        "{%0,%1,%2,%3}, {%4,%5,%6,%7}, {%8,%9}, {%0,%1,%2,%3};"
        : "+f"(c[0]), "+f"(c[1]), "+f"(c[2]), "+f"(c[3])
        : "r"(a[0]), "r"(a[1]), "r"(a[2]), "r"(a[3]), "r"(b0), "r"(b1));
}

// ---------------- GEMM config ----------------
#define BKC 32                       // K per chunk
#define LDS_T 40                     // padded SMEM row stride (bf16)
#define TILE_B (128 * LDS_T * 2)     // 10240 B per operand tile
#define STAGE_B (4 * TILE_B)         // 40960 B per stage (Ahi,Alo,Bhi,Blo)
#define SMEM_GEMM (2 * STAGE_B)      // 81920 B (2-stage)

// C[128x128 tile] = (Ahi+Alo) @ (Bhi+Blo)^T ; A [M,K] (lda), B [N,K] (ldb), C fp32 (ldc).
// K multiple of 32. 256 threads, warp grid 4(M) x 2(N), warp tile 32x64.
__device__ __forceinline__ void gemm_mma_body(
    const bf16* __restrict__ Ahi, const bf16* __restrict__ Alo,
    const bf16* __restrict__ Bhi, const bf16* __restrict__ Blo,
    float* __restrict__ C, int K, int lda, int ldb, int ldc) {
    extern __shared__ char smem[];
    const uint32_t sb = smem_u32(smem);
    const int tid = threadIdx.x;
    const int lid = tid & 31;
    const int warp_m = (tid >> 5) & 3;
    const int warp_n = tid >> 7;
    const int m0 = blockIdx.y * 128, n0 = blockIdx.x * 128;

    float acc[2][8][4];
#pragma unroll
    for (int mt = 0; mt < 2; mt++)
#pragma unroll
        for (int nt = 0; nt < 8; nt++)
#pragma unroll
            for (int j = 0; j < 4; j++) acc[mt][nt][j] = 0.0f;

    const int nch = K >> 5;

    // ---- chunk loader (cp.async, 16B lines) ----
    auto load_chunk = [&](int ch, int st) {
        const int k0 = ch << 5;
        const uint32_t base = sb + st * STAGE_B;
#pragma unroll
        for (int i = 0; i < 2; i++) {
            int idx = i * 256 + tid;          // 0..511
            int row = idx >> 2, c4 = idx & 3; // 4x16B per 32-col row
            uint32_t so = (uint32_t)(row * LDS_T + c4 * 8) * 2;
            size_t ga = (size_t)(m0 + row) * lda + k0 + c4 * 8;
            size_t gb = (size_t)(n0 + row) * ldb + k0 + c4 * 8;
            cp16(base + 0 * TILE_B + so, Ahi + ga);
            cp16(base + 1 * TILE_B + so, Alo + ga);
            cp16(base + 2 * TILE_B + so, Bhi + gb);
            cp16(base + 3 * TILE_B + so, Blo + gb);
        }
        CP_COMMIT();
    };

    load_chunk(0, 0);

    for (int ch = 0; ch < nch; ch++) {
        const int st = ch & 1;
        if (ch + 1 < nch) { load_chunk(ch + 1, st ^ 1); CP_WAIT(1); }
        else             { CP_WAIT(0); }
        __syncthreads();

        const uint32_t sA_hi = sb + st * STAGE_B;
        const uint32_t sA_lo = sA_hi + TILE_B;
        const uint32_t sB_hi = sA_lo + TILE_B;
        const uint32_t sB_lo = sB_hi + TILE_B;

#pragma unroll
        for (int ks = 0; ks < 32; ks += 16) {
            const int col = ks + ((lid >> 4) << 3);
            const uint32_t a_off = (uint32_t)((warp_m * 32 + (lid & 15)) * LDS_T + col) * 2;
            const uint32_t b_off = (uint32_t)((warp_n * 64 + (lid & 15)) * LDS_T + col) * 2;

            uint32_t Ah[2][4], Al[2][4], Bf[4][4];
            ldsm_x4(Ah[0], sA_hi + a_off);
            ldsm_x4(Ah[1], sA_hi + a_off + 16 * LDS_T * 2);
#pragma unroll
            for (int p = 0; p < 4; p++) ldsm_x4(Bf[p], sB_hi + b_off + p * 16 * LDS_T * 2);

            // pass 1: hi * hi
#pragma unroll
            for (int mt = 0; mt < 2; mt++)
#pragma unroll
                for (int nt = 0; nt < 8; nt++)
                    mma_bf16(acc[mt][nt], Ah[mt], Bf[nt >> 1][nt & 1], Bf[nt >> 1][(nt & 1) + 2]);

            // pass 2: lo * hi
            ldsm_x4(Al[0], sA_lo + a_off);
            ldsm_x4(Al[1], sA_lo + a_off + 16 * LDS_T * 2);
#pragma unroll
            for (int mt = 0; mt < 2; mt++)
#pragma unroll
                for (int nt = 0; nt < 8; nt++)
                    mma_bf16(acc[mt][nt], Al[mt], Bf[nt >> 1][nt & 1], Bf[nt >> 1][(nt & 1) + 2]);

            // pass 3: hi * lo (reuse Bf regs)
#pragma unroll
            for (int p = 0; p < 4; p++) ldsm_x4(Bf[p], sB_lo + b_off + p * 16 * LDS_T * 2);
#pragma unroll
            for (int mt = 0; mt < 2; mt++)
#pragma unroll
                for (int nt = 0; nt < 8; nt++)
                    mma_bf16(acc[mt][nt], Ah[mt], Bf[nt >> 1][nt & 1], Bf[nt >> 1][(nt & 1) + 2]);
        }
        __syncthreads();
    }

    // epilogue: direct float2 stores
#pragma unroll
    for (int mt = 0; mt < 2; mt++) {
        const int row = m0 + warp_m * 32 + mt * 16 + (lid >> 2);
#pragma unroll
        for (int nt = 0; nt < 8; nt++) {
            const int colx = n0 + warp_n * 64 + nt * 8 + (lid & 3) * 2;
            *(float2*)(C + (size_t)row * ldc + colx)       = make_float2(acc[mt][nt][0], acc[mt][nt][1]);
            *(float2*)(C + (size_t)(row + 8) * ldc + colx) = make_float2(acc[mt][nt][2], acc[mt][nt][3]);
        }
    }
}

__global__ void __launch_bounds__(256) k_gemm_mma(
    const bf16* __restrict__ Ahi, const bf16* __restrict__ Alo,
    const bf16* __restrict__ Bhi, const bf16* __restrict__ Blo,
    float* __restrict__ C, int K, int lda, int ldb, int ldc) {
    gemm_mma_body(Ahi, Alo, Bhi, Blo, C, K, lda, ldb, ldc);
}

__global__ void __launch_bounds__(256) k_qk_mma() {
    int bh = blockIdx.z;
    int b = bh >> 3, h = bh & 7, kv = h >> 1;
    gemm_mma_body(s_q_hi + (size_t)b * SS * QC + h * HD,
                  s_q_lo + (size_t)b * SS * QC + h * HD,
                  s_k_hi + (size_t)b * SS * KC + kv * HD,
                  s_k_lo + (size_t)b * SS * KC + kv * HD,
                  g_sc + (size_t)bh * SS * SS, HD, QC, KC, SS);
}

__global__ void __launch_bounds__(256) k_pv_mma() {
    int bh = blockIdx.z;
    int b = bh >> 3, h = bh & 7, kv = h >> 1;
    gemm_mma_body(s_p_hi + (size_t)bh * SS * SS,
                  s_p_lo + (size_t)bh * SS * SS,
                  s_vt_hi + (size_t)(b * NKV + kv) * HD * SS,
                  s_vt_lo + (size_t)(b * NKV + kv) * HD * SS,
                  g_o + (size_t)b * SS * QC + h * HD, SS, SS, SS, QC);
}

// ---------------- split / transpose / elementwise ----------------
__device__ __forceinline__ void split2(float v, bf16* hi, bf16* lo) {
    bf16 h = __float2bfloat16_rn(v);
    *hi = h;
    *lo = __float2bfloat16_rn(v - __bfloat162float(h));
}

// transpose+split: in fp32 [R,C] -> out bf16 [C,R] hi/lo. R,C multiples of 32.
__global__ void __launch_bounds__(256) k_tsplit(const float* __restrict__ in,
                                                bf16* __restrict__ ohi, bf16* __restrict__ olo,
                                                int R, int C) {
    __shared__ float t[32][33];
    int c0 = blockIdx.x * 32, r0 = blockIdx.y * 32;
    int tx = threadIdx.x & 31, ty = threadIdx.x >> 5;
#pragma unroll
    for (int i = 0; i < 4; i++)
        t[ty + i * 8][tx] = in[(size_t)(r0 + ty + i * 8) * C + c0 + tx];
    __syncthreads();
#pragma unroll
    for (int i = 0; i < 4; i++) {
        float v = t[tx][ty + i * 8];
        size_t o = (size_t)(c0 + ty + i * 8) * R + r0 + tx;
        split2(v, ohi + o, olo + o);
    }
}

// rmsnorm -> split
__global__ void __launch_bounds__(256) k_rms_split(const float* __restrict__ x,
                                                   const float* __restrict__ g,
                                                   bf16* __restrict__ ohi, bf16* __restrict__ olo) {
    int row = blockIdx.x;
    const float* xr = x + (size_t)row * HH;
    float s = 0.0f;
    for (int i = threadIdx.x; i < HH; i += 256) { float v = xr[i]; s = fmaf(v, v, s); }
    __shared__ float red[256];
    red[threadIdx.x] = s;
    __syncthreads();
    for (int off = 128; off > 0; off >>= 1) {
        if (threadIdx.x < off) red[threadIdx.x] += red[threadIdx.x + off];
        __syncthreads();
    }
    float rstd = rsqrtf(red[0] * (1.0f / HH) + RMS_EPS);
    size_t base = (size_t)row * HH;
    for (int i = threadIdx.x; i < HH; i += 256)
        split2(xr[i] * rstd * (1.0f + g[i]), ohi + base + i, olo + base + i);
}

// out = res + rmsnorm(y, g)   (fp32)
__global__ void __launch_bounds__(256) k_add_rms(const float* __restrict__ res,
                                                 const float* __restrict__ y,
                                                 const float* __restrict__ g,
                                                 float* __restrict__ out) {
    int row = blockIdx.x;
    const float* yr = y + (size_t)row * HH;
    float s = 0.0f;
    for (int i = threadIdx.x; i < HH; i += 256) { float v = yr[i]; s = fmaf(v, v, s); }
    __shared__ float red[256];
    red[threadIdx.x] = s;
    __syncthreads();
    for (int off = 128; off > 0; off >>= 1) {
        if (threadIdx.x < off) red[threadIdx.x] += red[threadIdx.x + off];
        __syncthreads();
    }
    float rstd = rsqrtf(red[0] * (1.0f / HH) + RMS_EPS);
    const float* rr = res + (size_t)row * HH;
    float* orow = out + (size_t)row * HH;
    for (int i = threadIdx.x; i < HH; i += 256)
        orow[i] = rr[i] + yr[i] * rstd * (1.0f + g[i]);
}

// RoPE on fp32 q/k, write split buffers
__global__ void __launch_bounds__(256) k_rope_split() {
    int idx = blockIdx.x * 256 + threadIdx.x;            // < MROWS*12*128
    int j = idx & 127;
    int hd = (idx >> 7) % 12;
    int row = idx / (12 * 128);
    int pos = row & (SS - 1);
    float inv = __powf(10000.0f, -(float)(2 * j) * (1.0f / HD));
    float fr = (float)pos * inv;
    float sn, cs;
    sincosf(fr, &sn, &cs);
    const float* base;
    bf16 *ohi, *olo;
    size_t off;
    if (hd < 8) {
        off = (size_t)row * QC + hd * HD;
        base = g_q + off; ohi = s_q_hi + off; olo = s_q_lo + off;
    } else {
        off = (size_t)row * KC + (hd - 8) * HD;
        base = g_k + off; ohi = s_k_hi + off; olo = s_k_lo + off;
    }
    float v0 = base[j], v1 = base[j + 128];
    split2(v0 * cs - v1 * sn, ohi + j, olo + j);
    split2(v1 * cs + v0 * sn, ohi + j + 128, olo + j + 128);
}

// V: fp32 [B,S,NKV,HD] -> bf16 split transposed [B*NKV, HD, S]
__global__ void __launch_bounds__(256) k_vtrans_split() {
    __shared__ float t[32][33];
    int bkv = blockIdx.z;
    int b = bkv >> 2, kv = bkv & 3;
    int d0 = blockIdx.x * 32, s0 = blockIdx.y * 32;
    int tx = threadIdx.x & 31, ty = threadIdx.x >> 5;
#pragma unroll
    for (int i = 0; i < 4; i++)
        t[ty + i * 8][tx] = g_v[(size_t)(b * SS + s0 + ty + i * 8) * KC + kv * HD + d0 + tx];
    __syncthreads();
#pragma unroll
    for (int i = 0; i < 4; i++) {
        float v = t[tx][ty + i * 8];
        size_t o = (size_t)bkv * HD * SS + (size_t)(d0 + ty + i * 8) * SS + s0 + tx;
        split2(v, s_vt_hi + o, s_vt_lo + o);
    }
}

// softmax with softcap + causal mask; reads g_sc fp32, writes p hi/lo
__global__ void __launch_bounds__(256) k_softmax_split() {
    int r = blockIdx.x;                 // bh*SS + qi
    int qi = r & (SS - 1);
    const float* row = g_sc + (size_t)r * SS;
    int t = threadIdx.x;
    float vals[8];
    float mx = -1e30f;
#pragma unroll
    for (int i = 0; i < 8; i++) {
        int j = t + i * 256;
        float s = row[j] * ATT_SCALE;
        s = SOFTCAP * tanhf(s * (1.0f / SOFTCAP));
        if (j > qi) s -= 1e9f;
        vals[i] = s;
        mx = fmaxf(mx, s);
    }
    __shared__ float red[256];
    red[t] = mx;
    __syncthreads();
    for (int off = 128; off > 0; off >>= 1) {
        if (t < off) red[t] = fmaxf(red[t], red[t + off]);
        __syncthreads();
    }
    mx = red[0];
    __syncthreads();
    float sum = 0.0f;
#pragma unroll
    for (int i = 0; i < 8; i++) { vals[i] = __expf(vals[i] - mx); sum += vals[i]; }
    red[t] = sum;
    __syncthreads();
    for (int off = 128; off > 0; off >>= 1) {
        if (t < off) red[t] += red[t + off];
        __syncthreads();
    }
    float inv = 1.0f / red[0];
    size_t base = (size_t)r * SS;
#pragma unroll
    for (int i = 0; i < 8; i++) {
        int j = t + i * 256;
        split2(vals[i] * inv, s_p_hi + base + j, s_p_lo + base + j);
    }
}

// plain fp32 -> split (for o)
__global__ void __launch_bounds__(256) k_split_o() {
    size_t i = (size_t)blockIdx.x * 256 + threadIdx.x;
    split2(g_o[i], s_o_hi + i, s_o_lo + i);
}

// GeGLU: act = gelu_tanh(gate) * up -> split
__global__ void __launch_bounds__(256) k_geglu_split() {
    size_t i = (size_t)blockIdx.x * 256 + threadIdx.x;
    float x = g_gate[i];
    float u = g_up[i];
    const float c0 = 0.7978845608028654f;
    float inner = c0 * fmaf(0.044715f * x * x, x, x);
    float act = 0.5f * x * (1.0f + tanhf(inner)) * u;
    split2(act, s_a_hi + i, s_a_lo + i);
}

// ---------------- launch ----------------
extern "C" void kernel_launch(void* const* d_in, const int* in_sizes, int n_in,
                              void* d_out, int out_size) {
    const float* x      = (const float*)d_in[0];
    // d_in[1] = mask (pure causal; applied analytically)
    const float* wq     = (const float*)d_in[2];
    const float* wk     = (const float*)d_in[3];
    const float* wv     = (const float*)d_in[4];
    const float* wo     = (const float*)d_in[5];
    const float* w_gate = (const float*)d_in[6];
    const float* w_up   = (const float*)d_in[7];
    const float* w_down = (const float*)d_in[8];
    const float* gin    = (const float*)d_in[9];
    const float* gpa    = (const float*)d_in[10];
    const float* gpf    = (const float*)d_in[11];
    const float* gpff   = (const float*)d_in[12];
    float* out = (float*)d_out;

    cudaFuncSetAttribute(k_gemm_mma, cudaFuncAttributeMaxDynamicSharedMemorySize, SMEM_GEMM);
    cudaFuncSetAttribute(k_qk_mma,   cudaFuncAttributeMaxDynamicSharedMemorySize, SMEM_GEMM);
    cudaFuncSetAttribute(k_pv_mma,   cudaFuncAttributeMaxDynamicSharedMemorySize, SMEM_GEMM);

#define SYM(p, s) void* p; cudaGetSymbolAddress(&p, s)
    SYM(p_hhi, s_h_hi);  SYM(p_hlo, s_h_lo);
    SYM(p_q, g_q);       SYM(p_k, g_k);      SYM(p_v, g_v);
    SYM(p_sc, g_sc);     SYM(p_o, g_o);
    SYM(p_ohi, s_o_hi);  SYM(p_olo, s_o_lo);
    SYM(p_attn, g_attn); SYM(p_h2, g_h2);
    SYM(p_fhi, s_f_hi);  SYM(p_flo, s_f_lo);
    SYM(p_gate, g_gate); SYM(p_up, g_up);
    SYM(p_ahi, s_a_hi);  SYM(p_alo, s_a_lo);
    SYM(p_mlp, g_mlp);
    SYM(p_wqh, w_qt_hi); SYM(p_wql, w_qt_lo);
    SYM(p_wkh, w_kt_hi); SYM(p_wkl, w_kt_lo);
    SYM(p_wvh, w_vt_hi); SYM(p_wvl, w_vt_lo);
    SYM(p_woh, w_ot_hi); SYM(p_wol, w_ot_lo);
    SYM(p_wgh, w_gt_hi); SYM(p_wgl, w_gt_lo);
    SYM(p_wuh, w_ut_hi); SYM(p_wul, w_ut_lo);
    SYM(p_wdh, w_dt_hi); SYM(p_wdl, w_dt_lo);
#undef SYM

    // weight transpose + bf16 split ([K,N] -> [N,K] hi/lo)
    k_tsplit<<<dim3(QC / 32, HH / 32), 256>>>(wq,     (bf16*)p_wqh, (bf16*)p_wql, HH, QC);
    k_tsplit<<<dim3(KC / 32, HH / 32), 256>>>(wk,     (bf16*)p_wkh, (bf16*)p_wkl, HH, KC);
    k_tsplit<<<dim3(KC / 32, HH / 32), 256>>>(wv,     (bf16*)p_wvh, (bf16*)p_wvl, HH, KC);
    k_tsplit<<<dim3(HH / 32, QC / 32), 256>>>(wo,     (bf16*)p_woh, (bf16*)p_wol, QC, HH);
    k_tsplit<<<dim3(FF / 32, HH / 32), 256>>>(w_gate, (bf16*)p_wgh, (bf16*)p_wgl, HH, FF);
    k_tsplit<<<dim3(FF / 32, HH / 32), 256>>>(w_up,   (bf16*)p_wuh, (bf16*)p_wul, HH, FF);
    k_tsplit<<<dim3(HH / 32, FF / 32), 256>>>(w_down, (bf16*)p_wdh, (bf16*)p_wdl, FF, HH);

    // 1. h = rmsnorm(x, g_in) -> split
    k_rms_split<<<MROWS, 256>>>(x, gin, (bf16*)p_hhi, (bf16*)p_hlo);

    // 2-4. q/k/v projections (fp32 out)
    k_gemm_mma<<<dim3(QC / 128, MROWS / 128), 256, SMEM_GEMM>>>(
        (bf16*)p_hhi, (bf16*)p_hlo, (bf16*)p_wqh, (bf16*)p_wql, (float*)p_q, HH, HH, HH, QC);
    k_gemm_mma<<<dim3(KC / 128, MROWS / 128), 256, SMEM_GEMM>>>(
        (bf16*)p_hhi, (bf16*)p_hlo, (bf16*)p_wkh, (bf16*)p_wkl, (float*)p_k, HH, HH, HH, KC);
    k_gemm_mma<<<dim3(KC / 128, MROWS / 128), 256, SMEM_GEMM>>>(
        (bf16*)p_hhi, (bf16*)p_hlo, (bf16*)p_wvh, (bf16*)p_wvl, (float*)p_v, HH, HH, HH, KC);

    // 5. RoPE -> split q/k; V transpose -> split
    k_rope_split<<<(MROWS * 12 * 128) / 256, 256>>>();
    k_vtrans_split<<<dim3(HD / 32, SS / 32, BB * NKV), 256>>>();

    // 6. scores = q @ k^T
    k_qk_mma<<<dim3(SS / 128, SS / 128, BB * NH), 256, SMEM_GEMM>>>();

    // 7. softcap + causal + softmax -> p split
    k_softmax_split<<<BB * NH * SS, 256>>>();

    // 8. o = p @ v
    k_pv_mma<<<dim3(HD / 128, SS / 128, BB * NH), 256, SMEM_GEMM>>>();

    // 9. attn_out = o @ wo
    k_split_o<<<(MROWS * QC) / 256, 256>>>();
    k_gemm_mma<<<dim3(HH / 128, MROWS / 128), 256, SMEM_GEMM>>>(
        (bf16*)p_ohi, (bf16*)p_olo, (bf16*)p_woh, (bf16*)p_wol, (float*)p_attn, QC, QC, QC, HH);

    // 10-11. h2 = x + rmsnorm(attn); f = rmsnorm(h2) -> split
    k_add_rms<<<MROWS, 256>>>(x, (float*)p_attn, gpa, (float*)p_h2);
    k_rms_split<<<MROWS, 256>>>((float*)p_h2, gpf, (bf16*)p_fhi, (bf16*)p_flo);

    // 12-13. gate/up
    k_gemm_mma<<<dim3(FF / 128, MROWS / 128), 256, SMEM_GEMM>>>(
        (bf16*)p_fhi, (bf16*)p_flo, (bf16*)p_wgh, (bf16*)p_wgl, (float*)p_gate, HH, HH, HH, FF);
    k_gemm_mma<<<dim3(FF / 128, MROWS / 128), 256, SMEM_GEMM>>>(
        (bf16*)p_fhi, (bf16*)p_flo, (bf16*)p_wuh, (bf16*)p_wul, (float*)p_up, HH, HH, HH, FF);

    // 14. GeGLU -> split
    k_geglu_split<<<(int)(((size_t)MROWS * FF) / 256), 256>>>();

    // 15. mlp = act @ w_down
    k_gemm_mma<<<dim3(HH / 128, MROWS / 128), 256, SMEM_GEMM>>>(
        (bf16*)p_ahi, (bf16*)p_alo, (bf16*)p_wdh, (bf16*)p_wdl, (float*)p_mlp, FF, FF, FF, HH);

    // 16. out = h2 + rmsnorm(mlp)
    k_add_rms<<<MROWS, 256>>>((float*)p_h2, (float*)p_mlp, gpff, out);
}

// round 10
// speedup vs baseline: 3.3930x; 1.0329x over previous
#include <cuda_runtime.h>
#include <cuda_bf16.h>
#include <math.h>
#include <stdint.h>

// ---------------- problem constants ----------------
#define BB 2
#define SS 2048
#define HH 2304
#define NH 8
#define NKV 4
#define HD 256
#define FF 9216
#define MROWS (BB * SS)          // 4096
#define QC (NH * HD)             // 2048
#define KC (NKV * HD)            // 1024
#define SOFTCAP 50.0f
#define ATT_SCALE 0.0625f
#define RMS_EPS 1e-6f

typedef __nv_bfloat16 bf16;

// ---------------- scratch (device globals; no allocations) ----------------
#define DEVBUF __device__ __align__(256)
DEVBUF bf16  s_h_hi [(size_t)MROWS * HH];   DEVBUF bf16 s_h_lo [(size_t)MROWS * HH];
DEVBUF float g_q    [(size_t)MROWS * QC];
DEVBUF float g_k    [(size_t)MROWS * KC];
DEVBUF float g_v    [(size_t)MROWS * KC];
DEVBUF bf16  s_q_hi [(size_t)MROWS * QC];   DEVBUF bf16 s_q_lo [(size_t)MROWS * QC];
DEVBUF bf16  s_k_hi [(size_t)MROWS * KC];   DEVBUF bf16 s_k_lo [(size_t)MROWS * KC];
DEVBUF bf16  s_vt_hi[(size_t)MROWS * KC];   DEVBUF bf16 s_vt_lo[(size_t)MROWS * KC];
DEVBUF float g_sc   [(size_t)BB * NH * SS * SS];
DEVBUF bf16  s_p_hi [(size_t)BB * NH * SS * SS];
DEVBUF bf16  s_p_lo [(size_t)BB * NH * SS * SS];
DEVBUF bf16  s_o_hi [(size_t)MROWS * QC];   DEVBUF bf16 s_o_lo [(size_t)MROWS * QC];
DEVBUF float g_attn [(size_t)MROWS * HH];
DEVBUF float g_h2   [(size_t)MROWS * HH];
DEVBUF bf16  s_f_hi [(size_t)MROWS * HH];   DEVBUF bf16 s_f_lo [(size_t)MROWS * HH];
DEVBUF float g_gate [(size_t)MROWS * FF];
DEVBUF float g_up   [(size_t)MROWS * FF];
DEVBUF bf16  s_a_hi [(size_t)MROWS * FF];   DEVBUF bf16 s_a_lo [(size_t)MROWS * FF];
DEVBUF float g_mlp  [(size_t)MROWS * HH];
// transposed + split weights ([N,K] K-major, bf16 hi/lo)
DEVBUF bf16 w_qt_hi[(size_t)QC * HH]; DEVBUF bf16 w_qt_lo[(size_t)QC * HH];
DEVBUF bf16 w_kt_hi[(size_t)KC * HH]; DEVBUF bf16 w_kt_lo[(size_t)KC * HH];
DEVBUF bf16 w_vt_hi[(size_t)KC * HH]; DEVBUF bf16 w_vt_lo[(size_t)KC * HH];
DEVBUF bf16 w_ot_hi[(size_t)HH * QC]; DEVBUF bf16 w_ot_lo[(size_t)HH * QC];
DEVBUF bf16 w_gt_hi[(size_t)FF * HH]; DEVBUF bf16 w_gt_lo[(size_t)FF * HH];
DEVBUF bf16 w_ut_hi[(size_t)FF * HH]; DEVBUF bf16 w_ut_lo[(size_t)FF * HH];
DEVBUF bf16 w_dt_hi[(size_t)HH * FF]; DEVBUF bf16 w_dt_lo[(size_t)HH * FF];

// ---------------- PTX helpers ----------------
__device__ __forceinline__ uint32_t smem_u32(const void* p) {
    uint32_t a;
    asm("{ .reg .u64 t; cvta.to.shared.u64 t, %1; cvt.u32.u64 %0, t; }" : "=r"(a) : "l"(p));
    return a;
}
__device__ __forceinline__ void cp16(uint32_t saddr, const void* g) {
    asm volatile("cp.async.cg.shared.global [%0], [%1], 16;" :: "r"(saddr), "l"(g));
}
#define CP_COMMIT() asm volatile("cp.async.commit_group;" ::: "memory")
#define CP_WAIT(n)  asm volatile("cp.async.wait_group %0;" :: "n"(n) : "memory")

__device__ __forceinline__ void ldsm_x4(uint32_t (&r)[4], uint32_t addr) {
    asm volatile("ldmatrix.sync.aligned.m8n8.x4.shared.b16 {%0,%1,%2,%3}, [%4];"
                 : "=r"(r[0]), "=r"(r[1]), "=r"(r[2]), "=r"(r[3]) : "r"(addr));
}
__device__ __forceinline__ void mma_bf16(float (&c)[4], const uint32_t (&a)[4],
                                         uint32_t b0, uint32_t b1) {
    asm volatile(
        "mma.sync.aligned.m16n8k16.row.col.f32.bf16.bf16.f32 "
        "{%0,%1,%2,%3}, {%4,%5,%6,%7}, {%8,%9}, {%0,%1,%2,%3};"
        : "+f"(c[0]), "+f"(c[1]), "+f"(c[2]), "+f"(c[3])
        : "r"(a[0]), "r"(a[1]), "r"(a[2]), "r"(a[3]), "r"(b0), "r"(b1));
}

__device__ __forceinline__ void split2(float v, bf16* hi, bf16* lo) {
    bf16 h = __float2bfloat16_rn(v);
    *hi = h;
    *lo = __float2bfloat16_rn(v - __bfloat162float(h));
}

// ---------------- GEMM config ----------------
// CTA tile 128(M) x 256(N) x 32(K-chunk), 512 threads (16 warps, 4x4),
// warp tile 32x64, 3-stage cp.async pipeline, LDS_T=40 (conflict-free ldmatrix).
#define LDS_T  40
#define TA_B   (128 * LDS_T * 2)          // 10240 B (A tile: 128 x 32 bf16)
#define TB_B   (256 * LDS_T * 2)          // 20480 B (B tile: 256 x 32 bf16)
#define SA_HI  0
#define SA_LO  (SA_HI + TA_B)
#define SB_HI  (SA_LO + TA_B)
#define SB_LO  (SB_HI + TB_B)
#define STAGE_B (2 * TA_B + 2 * TB_B)     // 61440 B
#define NSTAGE 3
#define SMEM_GEMM (NSTAGE * STAGE_B)      // 184320 B

// C[128 x 256 tile] = (Ahi+Alo) @ (Bhi+Blo)^T ; A [M,K] (lda), B [N,K] (ldb).
// SPLIT=false: write fp32 C (ldc). SPLIT=true: write bf16 hi/lo pair.
template<bool SPLIT>
__device__ __forceinline__ void gemm_mma_body(
    const bf16* __restrict__ Ahi, const bf16* __restrict__ Alo,
    const bf16* __restrict__ Bhi, const bf16* __restrict__ Blo,
    float* __restrict__ C, bf16* __restrict__ Chi, bf16* __restrict__ Clo,
    int K, int lda, int ldb, int ldc) {
    extern __shared__ char smem[];
    const uint32_t sb = smem_u32(smem);
    const int tid = threadIdx.x;
    const int lid = tid & 31;
    const int wid = tid >> 5;
    const int warp_m = wid & 3;
    const int warp_n = wid >> 2;
    const int m0 = blockIdx.y * 128, n0 = blockIdx.x * 256;

    float acc[2][8][4];
#pragma unroll
    for (int mt = 0; mt < 2; mt++)
#pragma unroll
        for (int nt = 0; nt < 8; nt++)
#pragma unroll
            for (int j = 0; j < 4; j++) acc[mt][nt][j] = 0.0f;

    const int nch = K >> 5;

    auto load_chunk = [&](int ch) {
        const int k0 = ch << 5;
        const uint32_t base = sb + (ch % NSTAGE) * STAGE_B;
        {   // A tiles: 128 rows x 32 cols, 512 x 16B lines per operand
            int row = tid >> 2, c4 = tid & 3;
            uint32_t so = (uint32_t)(row * LDS_T + c4 * 8) * 2;
            size_t ga = (size_t)(m0 + row) * lda + k0 + c4 * 8;
            cp16(base + SA_HI + so, Ahi + ga);
            cp16(base + SA_LO + so, Alo + ga);
        }
#pragma unroll
        for (int i = 0; i < 2; i++) {   // B tiles: 256 rows
            int idx = i * 512 + tid;
            int row = idx >> 2, c4 = idx & 3;
            uint32_t so = (uint32_t)(row * LDS_T + c4 * 8) * 2;
            size_t gb = (size_t)(n0 + row) * ldb + k0 + c4 * 8;
            cp16(base + SB_HI + so, Bhi + gb);
            cp16(base + SB_LO + so, Blo + gb);
        }
    };

    // prologue: 2 chunks in flight
    load_chunk(0); CP_COMMIT();
    if (nch > 1) load_chunk(1);
    CP_COMMIT();

    for (int ch = 0; ch < nch; ch++) {
        CP_WAIT(1);
        __syncthreads();
        if (ch + 2 < nch) load_chunk(ch + 2);
        CP_COMMIT();

        const uint32_t base = sb + (ch % NSTAGE) * STAGE_B;
        const uint32_t sA_hi = base + SA_HI, sA_lo = base + SA_LO;
        const uint32_t sB_hi = base + SB_HI, sB_lo = base + SB_LO;

#pragma unroll
        for (int ks = 0; ks < 32; ks += 16) {
            const int col = ks + ((lid >> 4) << 3);
            const uint32_t a_off = (uint32_t)((warp_m * 32 + (lid & 15)) * LDS_T + col) * 2;
            const uint32_t b_off = (uint32_t)((warp_n * 64 + (lid & 15)) * LDS_T + col) * 2;

            uint32_t Ah[2][4], Al[2][4], Bf[4][4];
            ldsm_x4(Ah[0], sA_hi + a_off);
            ldsm_x4(Ah[1], sA_hi + a_off + 16 * LDS_T * 2);
#pragma unroll
            for (int p = 0; p < 4; p++) ldsm_x4(Bf[p], sB_hi + b_off + p * 16 * LDS_T * 2);

            // pass 1: hi * hi
#pragma unroll
            for (int mt = 0; mt < 2; mt++)
#pragma unroll
                for (int nt = 0; nt < 8; nt++)
                    mma_bf16(acc[mt][nt], Ah[mt], Bf[nt >> 1][nt & 1], Bf[nt >> 1][(nt & 1) + 2]);

            // pass 2: lo * hi
            ldsm_x4(Al[0], sA_lo + a_off);
            ldsm_x4(Al[1], sA_lo + a_off + 16 * LDS_T * 2);
#pragma unroll
            for (int mt = 0; mt < 2; mt++)
#pragma unroll
                for (int nt = 0; nt < 8; nt++)
                    mma_bf16(acc[mt][nt], Al[mt], Bf[nt >> 1][nt & 1], Bf[nt >> 1][(nt & 1) + 2]);

            // pass 3: hi * lo
#pragma unroll
            for (int p = 0; p < 4; p++) ldsm_x4(Bf[p], sB_lo + b_off + p * 16 * LDS_T * 2);
#pragma unroll
            for (int mt = 0; mt < 2; mt++)
#pragma unroll
                for (int nt = 0; nt < 8; nt++)
                    mma_bf16(acc[mt][nt], Ah[mt], Bf[nt >> 1][nt & 1], Bf[nt >> 1][(nt & 1) + 2]);
        }
        __syncthreads();
    }

    // epilogue
#pragma unroll
    for (int mt = 0; mt < 2; mt++) {
        const int row = m0 + warp_m * 32 + mt * 16 + (lid >> 2);
#pragma unroll
        for (int nt = 0; nt < 8; nt++) {
            const int colx = n0 + warp_n * 64 + nt * 8 + (lid & 3) * 2;
            if (SPLIT) {
                bf16 h0, l0, h1, l1, h2, l2, h3, l3;
                split2(acc[mt][nt][0], &h0, &l0);
                split2(acc[mt][nt][1], &h1, &l1);
                split2(acc[mt][nt][2], &h2, &l2);
                split2(acc[mt][nt][3], &h3, &l3);
                __nv_bfloat162 vh, vl;
                vh.x = h0; vh.y = h1; vl.x = l0; vl.y = l1;
                *(__nv_bfloat162*)(Chi + (size_t)row * ldc + colx) = vh;
                *(__nv_bfloat162*)(Clo + (size_t)row * ldc + colx) = vl;
                vh.x = h2; vh.y = h3; vl.x = l2; vl.y = l3;
                *(__nv_bfloat162*)(Chi + (size_t)(row + 8) * ldc + colx) = vh;
                *(__nv_bfloat162*)(Clo + (size_t)(row + 8) * ldc + colx) = vl;
            } else {
                *(float2*)(C + (size_t)row * ldc + colx) =
                    make_float2(acc[mt][nt][0], acc[mt][nt][1]);
                *(float2*)(C + (size_t)(row + 8) * ldc + colx) =
                    make_float2(acc[mt][nt][2], acc[mt][nt][3]);
            }
        }
    }
}

__global__ void __launch_bounds__(512, 1) k_gemm_mma(
    const bf16* __restrict__ Ahi, const bf16* __restrict__ Alo,
    const bf16* __restrict__ Bhi, const bf16* __restrict__ Blo,
    float* __restrict__ C, int K, int lda, int ldb, int ldc) {
    gemm_mma_body<false>(Ahi, Alo, Bhi, Blo, C, nullptr, nullptr, K, lda, ldb, ldc);
}

// causal QK: skip tiles entirely above the diagonal
__global__ void __launch_bounds__(512, 1) k_qk_mma() {
    if (2 * blockIdx.x > blockIdx.y) return;   // n0 > m0+127
    int bh = blockIdx.z;
    int b = bh >> 3, h = bh & 7, kv = h >> 1;
    gemm_mma_body<false>(s_q_hi + (size_t)b * SS * QC + h * HD,
                         s_q_lo + (size_t)b * SS * QC + h * HD,
                         s_k_hi + (size_t)b * SS * KC + kv * HD,
                         s_k_lo + (size_t)b * SS * KC + kv * HD,
                         g_sc + (size_t)bh * SS * SS, nullptr, nullptr,
                         HD, QC, KC, SS);
}

// PV with causal K-limit; writes o hi/lo split directly
__global__ void __launch_bounds__(512, 1) k_pv_mma() {
    int bh = blockIdx.z;
    int b = bh >> 3, h = bh & 7, kv = h >> 1;
    int klim = (blockIdx.y + 1) * 128;
    if (klim > SS) klim = SS;
    gemm_mma_body<true>(s_p_hi + (size_t)bh * SS * SS,
                        s_p_lo + (size_t)bh * SS * SS,
                        s_vt_hi + (size_t)(b * NKV + kv) * HD * SS,
                        s_vt_lo + (size_t)(b * NKV + kv) * HD * SS,
                        nullptr,
                        s_o_hi + (size_t)b * SS * QC + h * HD,
                        s_o_lo + (size_t)b * SS * QC + h * HD,
                        klim, SS, SS, QC);
}

// ---------------- split / transpose / elementwise ----------------
// transpose+split: in fp32 [R,C] -> out bf16 [C,R] hi/lo. R,C multiples of 32.
__global__ void __launch_bounds__(256) k_tsplit(const float* __restrict__ in,
                                                bf16* __restrict__ ohi, bf16* __restrict__ olo,
                                                int R, int C) {
    __shared__ float t[32][33];
    int c0 = blockIdx.x * 32, r0 = blockIdx.y * 32;
    int tx = threadIdx.x & 31, ty = threadIdx.x >> 5;
#pragma unroll
    for (int i = 0; i < 4; i++)
        t[ty + i * 8][tx] = in[(size_t)(r0 + ty + i * 8) * C + c0 + tx];
    __syncthreads();
#pragma unroll
    for (int i = 0; i < 4; i++) {
        float v = t[tx][ty + i * 8];
        size_t o = (size_t)(c0 + ty + i * 8) * R + r0 + tx;
        split2(v, ohi + o, olo + o);
    }
}

// rmsnorm -> split
__global__ void __launch_bounds__(256) k_rms_split(const float* __restrict__ x,
                                                   const float* __restrict__ g,
                                                   bf16* __restrict__ ohi, bf16* __restrict__ olo) {
    int row = blockIdx.x;
    const float* xr = x + (size_t)row * HH;
    float s = 0.0f;
    for (int i = threadIdx.x; i < HH; i += 256) { float v = xr[i]; s = fmaf(v, v, s); }
    __shared__ float red[256];
    red[threadIdx.x] = s;
    __syncthreads();
    for (int off = 128; off > 0; off >>= 1) {
        if (threadIdx.x < off) red[threadIdx.x] += red[threadIdx.x + off];
        __syncthreads();
    }
    float rstd = rsqrtf(red[0] * (1.0f / HH) + RMS_EPS);
    size_t base = (size_t)row * HH;
    for (int i = threadIdx.x; i < HH; i += 256)
        split2(xr[i] * rstd * (1.0f + g[i]), ohi + base + i, olo + base + i);
}

// out = res + rmsnorm(y, g)   (fp32)
__global__ void __launch_bounds__(256) k_add_rms(const float* __restrict__ res,
                                                 const float* __restrict__ y,
                                                 const float* __restrict__ g,
                                                 float* __restrict__ out) {
    int row = blockIdx.x;
    const float* yr = y + (size_t)row * HH;
    float s = 0.0f;
    for (int i = threadIdx.x; i < HH; i += 256) { float v = yr[i]; s = fmaf(v, v, s); }
    __shared__ float red[256];
    red[threadIdx.x] = s;
    __syncthreads();
    for (int off = 128; off > 0; off >>= 1) {
        if (threadIdx.x < off) red[threadIdx.x] += red[threadIdx.x + off];
        __syncthreads();
    }
    float rstd = rsqrtf(red[0] * (1.0f / HH) + RMS_EPS);
    const float* rr = res + (size_t)row * HH;
    float* orow = out + (size_t)row * HH;
    for (int i = threadIdx.x; i < HH; i += 256)
        orow[i] = rr[i] + yr[i] * rstd * (1.0f + g[i]);
}

// RoPE on fp32 q/k, write split buffers
__global__ void __launch_bounds__(256) k_rope_split() {
    int idx = blockIdx.x * 256 + threadIdx.x;            // < MROWS*12*128
    int j = idx & 127;
    int hd = (idx >> 7) % 12;
    int row = idx / (12 * 128);
    int pos = row & (SS - 1);
    float inv = __powf(10000.0f, -(float)(2 * j) * (1.0f / HD));
    float fr = (float)pos * inv;
    float sn, cs;
    sincosf(fr, &sn, &cs);
    const float* base;
    bf16 *ohi, *olo;
    size_t off;
    if (hd < 8) {
        off = (size_t)row * QC + hd * HD;
        base = g_q + off; ohi = s_q_hi + off; olo = s_q_lo + off;
    } else {
        off = (size_t)row * KC + (hd - 8) * HD;
        base = g_k + off; ohi = s_k_hi + off; olo = s_k_lo + off;
    }
    float v0 = base[j], v1 = base[j + 128];
    split2(v0 * cs - v1 * sn, ohi + j, olo + j);
    split2(v1 * cs + v0 * sn, ohi + j + 128, olo + j + 128);
}

// V: fp32 [B,S,NKV,HD] -> bf16 split transposed [B*NKV, HD, S]
__global__ void __launch_bounds__(256) k_vtrans_split() {
    __shared__ float t[32][33];
    int bkv = blockIdx.z;
    int b = bkv >> 2, kv = bkv & 3;
    int d0 = blockIdx.x * 32, s0 = blockIdx.y * 32;
    int tx = threadIdx.x & 31, ty = threadIdx.x >> 5;
#pragma unroll
    for (int i = 0; i < 4; i++)
        t[ty + i * 8][tx] = g_v[(size_t)(b * SS + s0 + ty + i * 8) * KC + kv * HD + d0 + tx];
    __syncthreads();
#pragma unroll
    for (int i = 0; i < 4; i++) {
        float v = t[tx][ty + i * 8];
        size_t o = (size_t)bkv * HD * SS + (size_t)(d0 + ty + i * 8) * SS + s0 + tx;
        split2(v, s_vt_hi + o, s_vt_lo + o);
    }
}

// softmax (softcap + causal): only j <= qi read; zero-fill up to 128-boundary
__global__ void __launch_bounds__(256) k_softmax_split() {
    int r = blockIdx.x;                 // bh*SS + qi
    int qi = r & (SS - 1);
    int nr = ((qi >> 7) + 1) << 7;      // elements to write (multiple of 128)
    const float* row = g_sc + (size_t)r * SS;
    int t = threadIdx.x;
    float vals[8];
    float mx = -1e30f;
    int it = 0;
    for (int j = t; j < nr; j += 256, it++) {
        float s = -1e30f;
        if (j <= qi) {
            s = row[j] * ATT_SCALE;
            s = SOFTCAP * tanhf(s * (1.0f / SOFTCAP));
            mx = fmaxf(mx, s);
        }
        vals[it] = s;
    }
    __shared__ float red[256];
    red[t] = mx;
    __syncthreads();
    for (int off = 128; off > 0; off >>= 1) {
        if (t < off) red[t] = fmaxf(red[t], red[t + off]);
        __syncthreads();
    }
    mx = red[0];
    __syncthreads();
    float sum = 0.0f;
    it = 0;
    for (int j = t; j < nr; j += 256, it++) {
        float e = (vals[it] > -1e29f) ? __expf(vals[it] - mx) : 0.0f;
        vals[it] = e;
        sum += e;
    }
    red[t] = sum;
    __syncthreads();
    for (int off = 128; off > 0; off >>= 1) {
        if (t < off) red[t] += red[t + off];
        __syncthreads();
    }
    float inv = 1.0f / red[0];
    size_t base = (size_t)r * SS;
    it = 0;
    for (int j = t; j < nr; j += 256, it++)
        split2(vals[it] * inv, s_p_hi + base + j, s_p_lo + base + j);
}

// GeGLU: act = gelu_tanh(gate) * up -> split
__global__ void __launch_bounds__(256) k_geglu_split() {
    size_t i = (size_t)blockIdx.x * 256 + threadIdx.x;
    float x = g_gate[i];
    float u = g_up[i];
    const float c0 = 0.7978845608028654f;
    float inner = c0 * fmaf(0.044715f * x * x, x, x);
    float act = 0.5f * x * (1.0f + tanhf(inner)) * u;
    split2(act, s_a_hi + i, s_a_lo + i);
}

// ---------------- launch ----------------
extern "C" void kernel_launch(void* const* d_in, const int* in_sizes, int n_in,
                              void* d_out, int out_size) {
    const float* x      = (const float*)d_in[0];
    // d_in[1] = mask (pure causal; applied analytically)
    const float* wq     = (const float*)d_in[2];
    const float* wk     = (const float*)d_in[3];
    const float* wv     = (const float*)d_in[4];
    const float* wo     = (const float*)d_in[5];
    const float* w_gate = (const float*)d_in[6];
    const float* w_up   = (const float*)d_in[7];
    const float* w_down = (const float*)d_in[8];
    const float* gin    = (const float*)d_in[9];
    const float* gpa    = (const float*)d_in[10];
    const float* gpf    = (const float*)d_in[11];
    const float* gpff   = (const float*)d_in[12];
    float* out = (float*)d_out;

    cudaFuncSetAttribute(k_gemm_mma, cudaFuncAttributeMaxDynamicSharedMemorySize, SMEM_GEMM);
    cudaFuncSetAttribute(k_qk_mma,   cudaFuncAttributeMaxDynamicSharedMemorySize, SMEM_GEMM);
    cudaFuncSetAttribute(k_pv_mma,   cudaFuncAttributeMaxDynamicSharedMemorySize, SMEM_GEMM);

#define SYM(p, s) void* p; cudaGetSymbolAddress(&p, s)
    SYM(p_hhi, s_h_hi);  SYM(p_hlo, s_h_lo);
    SYM(p_q, g_q);       SYM(p_k, g_k);      SYM(p_v, g_v);
    SYM(p_attn, g_attn); SYM(p_h2, g_h2);
    SYM(p_fhi, s_f_hi);  SYM(p_flo, s_f_lo);
    SYM(p_gate, g_gate); SYM(p_up, g_up);
    SYM(p_ahi, s_a_hi);  SYM(p_alo, s_a_lo);
    SYM(p_ohi, s_o_hi);  SYM(p_olo, s_o_lo);
    SYM(p_mlp, g_mlp);
    SYM(p_wqh, w_qt_hi); SYM(p_wql, w_qt_lo);
    SYM(p_wkh, w_kt_hi); SYM(p_wkl, w_kt_lo);
    SYM(p_wvh, w_vt_hi); SYM(p_wvl, w_vt_lo);
    SYM(p_woh, w_ot_hi); SYM(p_wol, w_ot_lo);
    SYM(p_wgh, w_gt_hi); SYM(p_wgl, w_gt_lo);
    SYM(p_wuh, w_ut_hi); SYM(p_wul, w_ut_lo);
    SYM(p_wdh, w_dt_hi); SYM(p_wdl, w_dt_lo);
#undef SYM

    // launches 0-4 (so launch #5 = Q-projection GEMM, for ncu -s 5 -c 1)
    k_tsplit<<<dim3(QC / 32, HH / 32), 256>>>(wq, (bf16*)p_wqh, (bf16*)p_wql, HH, QC);   // 0
    k_tsplit<<<dim3(KC / 32, HH / 32), 256>>>(wk, (bf16*)p_wkh, (bf16*)p_wkl, HH, KC);   // 1
    k_tsplit<<<dim3(KC / 32, HH / 32), 256>>>(wv, (bf16*)p_wvh, (bf16*)p_wvl, HH, KC);   // 2
    k_tsplit<<<dim3(HH / 32, QC / 32), 256>>>(wo, (bf16*)p_woh, (bf16*)p_wol, QC, HH);   // 3
    k_rms_split<<<MROWS, 256>>>(x, gin, (bf16*)p_hhi, (bf16*)p_hlo);                     // 4

    // 5: Q projection (ncu target)
    k_gemm_mma<<<dim3(QC / 256, MROWS / 128), 512, SMEM_GEMM>>>(
        (bf16*)p_hhi, (bf16*)p_hlo, (bf16*)p_wqh, (bf16*)p_wql, (float*)p_q, HH, HH, HH, QC);
    k_gemm_mma<<<dim3(KC / 256, MROWS / 128), 512, SMEM_GEMM>>>(
        (bf16*)p_hhi, (bf16*)p_hlo, (bf16*)p_wkh, (bf16*)p_wkl, (float*)p_k, HH, HH, HH, KC);
    k_gemm_mma<<<dim3(KC / 256, MROWS / 128), 512, SMEM_GEMM>>>(
        (bf16*)p_hhi, (bf16*)p_hlo, (bf16*)p_wvh, (bf16*)p_wvl, (float*)p_v, HH, HH, HH, KC);

    // remaining weight splits (overlap-friendly placement)
    k_tsplit<<<dim3(FF / 32, HH / 32), 256>>>(w_gate, (bf16*)p_wgh, (bf16*)p_wgl, HH, FF);
    k_tsplit<<<dim3(FF / 32, HH / 32), 256>>>(w_up,   (bf16*)p_wuh, (bf16*)p_wul, HH, FF);
    k_tsplit<<<dim3(HH / 32, FF / 32), 256>>>(w_down, (bf16*)p_wdh, (bf16*)p_wdl, FF, HH);

    // RoPE -> split q/k; V transpose -> split
    k_rope_split<<<(MROWS * 12 * 128) / 256, 256>>>();
    k_vtrans_split<<<dim3(HD / 32, SS / 32, BB * NKV), 256>>>();

    // scores = q @ k^T (causal tiles only)
    k_qk_mma<<<dim3(SS / 256, SS / 128, BB * NH), 512, SMEM_GEMM>>>();

    // softcap + causal + softmax -> p split
    k_softmax_split<<<BB * NH * SS, 256>>>();

    // o = p @ v (causal K-limit, split output fused)
    k_pv_mma<<<dim3(HD / 256, SS / 128, BB * NH), 512, SMEM_GEMM>>>();

    // attn_out = o @ wo
    k_gemm_mma<<<dim3(HH / 256, MROWS / 128), 512, SMEM_GEMM>>>(
        (bf16*)p_ohi, (bf16*)p_olo, (bf16*)p_woh, (bf16*)p_wol, (float*)p_attn, QC, QC, QC, HH);

    // h2 = x + rmsnorm(attn); f = rmsnorm(h2) -> split
    k_add_rms<<<MROWS, 256>>>(x, (float*)p_attn, gpa, (float*)p_h2);
    k_rms_split<<<MROWS, 256>>>((float*)p_h2, gpf, (bf16*)p_fhi, (bf16*)p_flo);

    // gate/up
    k_gemm_mma<<<dim3(FF / 256, MROWS / 128), 512, SMEM_GEMM>>>(
        (bf16*)p_fhi, (bf16*)p_flo, (bf16*)p_wgh, (bf16*)p_wgl, (float*)p_gate, HH, HH, HH, FF);
    k_gemm_mma<<<dim3(FF / 256, MROWS / 128), 512, SMEM_GEMM>>>(
        (bf16*)p_fhi, (bf16*)p_flo, (bf16*)p_wuh, (bf16*)p_wul, (float*)p_up, HH, HH, HH, FF);

    // GeGLU -> split
    k_geglu_split<<<(int)(((size_t)MROWS * FF) / 256), 256>>>();

    // mlp = act @ w_down
    k_gemm_mma<<<dim3(HH / 256, MROWS / 128), 512, SMEM_GEMM>>>(
        (bf16*)p_ahi, (bf16*)p_alo, (bf16*)p_wdh, (bf16*)p_wdl, (float*)p_mlp, FF, FF, FF, HH);

    // out = h2 + rmsnorm(mlp)
    k_add_rms<<<MROWS, 256>>>((float*)p_h2, (float*)p_mlp, gpff, out);
}

// round 11
// speedup vs baseline: 8.0177x; 2.3630x over previous
#include <cuda_runtime.h>
#include <cuda_fp16.h>
#include <math.h>
#include <stdint.h>

// ---------------- problem constants ----------------
#define BB 2
#define SS 2048
#define HH 2304
#define NH 8
#define NKV 4
#define HD 256
#define FF 9216
#define MROWS (BB * SS)          // 4096
#define QC (NH * HD)             // 2048
#define KC (NKV * HD)            // 1024
#define SOFTCAP 50.0f
#define ATT_SCALE 0.0625f
#define RMS_EPS 1e-6f

typedef __half f16;

// ---------------- scratch (device globals; no allocations) ----------------
#define DEVBUF __device__ __align__(256)
DEVBUF f16   s_h   [(size_t)MROWS * HH];
DEVBUF float g_q   [(size_t)MROWS * QC];
DEVBUF float g_k   [(size_t)MROWS * KC];
DEVBUF float g_v   [(size_t)MROWS * KC];
DEVBUF f16   s_q_hi[(size_t)MROWS * QC];  DEVBUF f16 s_q_lo[(size_t)MROWS * QC];
DEVBUF f16   s_k_hi[(size_t)MROWS * KC];  DEVBUF f16 s_k_lo[(size_t)MROWS * KC];
DEVBUF f16   s_vt  [(size_t)MROWS * KC];
DEVBUF float g_sc  [(size_t)BB * NH * SS * SS];
DEVBUF f16   s_p   [(size_t)BB * NH * SS * SS];
DEVBUF f16   s_o   [(size_t)MROWS * QC];
DEVBUF float g_attn[(size_t)MROWS * HH];
DEVBUF float g_h2  [(size_t)MROWS * HH];
DEVBUF f16   s_f   [(size_t)MROWS * HH];
DEVBUF float g_gate[(size_t)MROWS * FF];
DEVBUF float g_up  [(size_t)MROWS * FF];
DEVBUF f16   s_a   [(size_t)MROWS * FF];
DEVBUF float g_mlp [(size_t)MROWS * HH];
// transposed weights ([N,K] K-major, single fp16)
DEVBUF f16 w_qt[(size_t)QC * HH];
DEVBUF f16 w_kt[(size_t)KC * HH];
DEVBUF f16 w_vt[(size_t)KC * HH];
DEVBUF f16 w_ot[(size_t)HH * QC];
DEVBUF f16 w_gt[(size_t)FF * HH];
DEVBUF f16 w_ut[(size_t)FF * HH];
DEVBUF f16 w_dt[(size_t)HH * FF];

// ---------------- PTX helpers ----------------
__device__ __forceinline__ uint32_t smem_u32(const void* p) {
    uint32_t a;
    asm("{ .reg .u64 t; cvta.to.shared.u64 t, %1; cvt.u32.u64 %0, t; }" : "=r"(a) : "l"(p));
    return a;
}
__device__ __forceinline__ void cp16(uint32_t saddr, const void* g) {
    asm volatile("cp.async.cg.shared.global [%0], [%1], 16;" :: "r"(saddr), "l"(g));
}
#define CP_COMMIT() asm volatile("cp.async.commit_group;" ::: "memory")

__device__ __forceinline__ void ldsm_x4(uint32_t (&r)[4], uint32_t addr) {
    asm volatile("ldmatrix.sync.aligned.m8n8.x4.shared.b16 {%0,%1,%2,%3}, [%4];"
                 : "=r"(r[0]), "=r"(r[1]), "=r"(r[2]), "=r"(r[3]) : "r"(addr));
}
__device__ __forceinline__ void mma_f16(float (&c)[4], const uint32_t (&a)[4],
                                        uint32_t b0, uint32_t b1) {
    asm volatile(
        "mma.sync.aligned.m16n8k16.row.col.f32.f16.f16.f32 "
        "{%0,%1,%2,%3}, {%4,%5,%6,%7}, {%8,%9}, {%0,%1,%2,%3};"
        : "+f"(c[0]), "+f"(c[1]), "+f"(c[2]), "+f"(c[3])
        : "r"(a[0]), "r"(a[1]), "r"(a[2]), "r"(a[3]), "r"(b0), "r"(b1));
}

__device__ __forceinline__ void split2h(float v, f16* hi, f16* lo) {
    f16 h = __float2half_rn(v);
    *hi = h;
    *lo = __float2half_rn(v - __half2float(h));
}

// ---------------- GEMM config ----------------
// CTA tile 128(M) x 256(N) x 32(K-chunk), 512 threads (16 warps, 4x4),
// warp tile 32x64, cp.async multi-stage, LDS_T=40 (conflict-free ldmatrix).
#define LDS_T  40
#define TA_B   (128 * LDS_T * 2)          // 10240 B
#define TB_B   (256 * LDS_T * 2)          // 20480 B
#define SMEM_G1 (4 * (TA_B + TB_B))       // 122880 B (1-pass, 4 stages)
#define SMEM_G3 (3 * 2 * (TA_B + TB_B))   // 184320 B (3-pass, 3 stages)

// C[128 x 256 tile]. PASSES=1: C = A @ B^T (single fp16 operands).
// PASSES=3: C = (Ahi+Alo) @ (Bhi+Blo)^T  (drops lo*lo).
// OUT_HALF: write fp16 Ch instead of fp32 C.
template<int PASSES, bool OUT_HALF>
__device__ __forceinline__ void gemm_body(
    const f16* __restrict__ Ahi, const f16* __restrict__ Alo,
    const f16* __restrict__ Bhi, const f16* __restrict__ Blo,
    float* __restrict__ C, f16* __restrict__ Ch,
    int K, int lda, int ldb, int ldc) {
    constexpr int SAHI = 0;
    constexpr int SALO = (PASSES == 3) ? TA_B : 0;
    constexpr int SBHI = (PASSES == 3) ? 2 * TA_B : TA_B;
    constexpr int SBLO = (PASSES == 3) ? 2 * TA_B + TB_B : 0;
    constexpr int STAGE = (PASSES == 3) ? 2 * (TA_B + TB_B) : (TA_B + TB_B);
    constexpr int NST = (PASSES == 3) ? 3 : 4;

    extern __shared__ char smem[];
    const uint32_t sb = smem_u32(smem);
    const int tid = threadIdx.x;
    const int lid = tid & 31;
    const int wid = tid >> 5;
    const int warp_m = wid & 3;
    const int warp_n = wid >> 2;
    const int m0 = blockIdx.y * 128, n0 = blockIdx.x * 256;

    float acc[2][8][4];
#pragma unroll
    for (int mt = 0; mt < 2; mt++)
#pragma unroll
        for (int nt = 0; nt < 8; nt++)
#pragma unroll
            for (int j = 0; j < 4; j++) acc[mt][nt][j] = 0.0f;

    const int nch = K >> 5;

    auto load_chunk = [&](int ch) {
        const int k0 = ch << 5;
        const uint32_t base = sb + (ch % NST) * STAGE;
        {   // A: 128 rows x 32 cols = 512 x 16B lines
            int row = tid >> 2, c4 = tid & 3;
            uint32_t so = (uint32_t)(row * LDS_T + c4 * 8) * 2;
            size_t ga = (size_t)(m0 + row) * lda + k0 + c4 * 8;
            cp16(base + SAHI + so, Ahi + ga);
            if (PASSES == 3) cp16(base + SALO + so, Alo + ga);
        }
#pragma unroll
        for (int i = 0; i < 2; i++) {   // B: 256 rows
            int idx = i * 512 + tid;
            int row = idx >> 2, c4 = idx & 3;
            uint32_t so = (uint32_t)(row * LDS_T + c4 * 8) * 2;
            size_t gb = (size_t)(n0 + row) * ldb + k0 + c4 * 8;
            cp16(base + SBHI + so, Bhi + gb);
            if (PASSES == 3) cp16(base + SBLO + so, Blo + gb);
        }
    };

    // prologue: NST-1 chunks in flight
#pragma unroll
    for (int i = 0; i < NST - 1; i++) {
        if (i < nch) load_chunk(i);
        CP_COMMIT();
    }

    for (int ch = 0; ch < nch; ch++) {
        asm volatile("cp.async.wait_group %0;" :: "n"(NST - 2) : "memory");
        __syncthreads();
        if (ch + NST - 1 < nch) load_chunk(ch + NST - 1);
        CP_COMMIT();

        const uint32_t base = sb + (ch % NST) * STAGE;
        const uint32_t sA_hi = base + SAHI, sA_lo = base + SALO;
        const uint32_t sB_hi = base + SBHI, sB_lo = base + SBLO;

#pragma unroll
        for (int ks = 0; ks < 32; ks += 16) {
            const int col = ks + ((lid >> 4) << 3);
            const uint32_t a_off = (uint32_t)((warp_m * 32 + (lid & 15)) * LDS_T + col) * 2;
            const uint32_t b_off = (uint32_t)((warp_n * 64 + (lid & 15)) * LDS_T + col) * 2;

            uint32_t Ah[2][4], Bf[4][4];
            ldsm_x4(Ah[0], sA_hi + a_off);
            ldsm_x4(Ah[1], sA_hi + a_off + 16 * LDS_T * 2);
#pragma unroll
            for (int p = 0; p < 4; p++) ldsm_x4(Bf[p], sB_hi + b_off + p * 16 * LDS_T * 2);

            // pass 1: hi * hi
#pragma unroll
            for (int mt = 0; mt < 2; mt++)
#pragma unroll
                for (int nt = 0; nt < 8; nt++)
                    mma_f16(acc[mt][nt], Ah[mt], Bf[nt >> 1][nt & 1], Bf[nt >> 1][(nt & 1) + 2]);

            if (PASSES == 3) {
                // pass 2: lo * hi
                uint32_t Al[2][4];
                ldsm_x4(Al[0], sA_lo + a_off);
                ldsm_x4(Al[1], sA_lo + a_off + 16 * LDS_T * 2);
#pragma unroll
                for (int mt = 0; mt < 2; mt++)
#pragma unroll
                    for (int nt = 0; nt < 8; nt++)
                        mma_f16(acc[mt][nt], Al[mt], Bf[nt >> 1][nt & 1], Bf[nt >> 1][(nt & 1) + 2]);
                // pass 3: hi * lo
#pragma unroll
                for (int p = 0; p < 4; p++) ldsm_x4(Bf[p], sB_lo + b_off + p * 16 * LDS_T * 2);
#pragma unroll
                for (int mt = 0; mt < 2; mt++)
#pragma unroll
                    for (int nt = 0; nt < 8; nt++)
                        mma_f16(acc[mt][nt], Ah[mt], Bf[nt >> 1][nt & 1], Bf[nt >> 1][(nt & 1) + 2]);
            }
        }
        __syncthreads();
    }

    // epilogue
#pragma unroll
    for (int mt = 0; mt < 2; mt++) {
        const int row = m0 + warp_m * 32 + mt * 16 + (lid >> 2);
#pragma unroll
        for (int nt = 0; nt < 8; nt++) {
            const int colx = n0 + warp_n * 64 + nt * 8 + (lid & 3) * 2;
            if (OUT_HALF) {
                __half2 v0, v1;
                v0.x = __float2half_rn(acc[mt][nt][0]);
                v0.y = __float2half_rn(acc[mt][nt][1]);
                v1.x = __float2half_rn(acc[mt][nt][2]);
                v1.y = __float2half_rn(acc[mt][nt][3]);
                *(__half2*)(Ch + (size_t)row * ldc + colx)       = v0;
                *(__half2*)(Ch + (size_t)(row + 8) * ldc + colx) = v1;
            } else {
                *(float2*)(C + (size_t)row * ldc + colx) =
                    make_float2(acc[mt][nt][0], acc[mt][nt][1]);
                *(float2*)(C + (size_t)(row + 8) * ldc + colx) =
                    make_float2(acc[mt][nt][2], acc[mt][nt][3]);
            }
        }
    }
}

// single-pass fp16 GEMM, fp32 out
__global__ void __launch_bounds__(512, 1) k_gemm(
    const f16* __restrict__ A, const f16* __restrict__ B,
    float* __restrict__ C, int K, int lda, int ldb, int ldc) {
    gemm_body<1, false>(A, nullptr, B, nullptr, C, nullptr, K, lda, ldb, ldc);
}

// causal QK: 3-pass fp16 split (exact-ish scores), skip upper-triangle tiles
__global__ void __launch_bounds__(512, 1) k_qk() {
    if (2 * blockIdx.x > blockIdx.y) return;
    int bh = blockIdx.z;
    int b = bh >> 3, h = bh & 7, kv = h >> 1;
    gemm_body<3, false>(s_q_hi + (size_t)b * SS * QC + h * HD,
                        s_q_lo + (size_t)b * SS * QC + h * HD,
                        s_k_hi + (size_t)b * SS * KC + kv * HD,
                        s_k_lo + (size_t)b * SS * KC + kv * HD,
                        g_sc + (size_t)bh * SS * SS, nullptr,
                        HD, QC, KC, SS);
}

// PV: single-pass fp16, causal K-limit, fp16 out (o)
__global__ void __launch_bounds__(512, 1) k_pv() {
    int bh = blockIdx.z;
    int b = bh >> 3, h = bh & 7, kv = h >> 1;
    int klim = (blockIdx.y + 1) * 128;
    if (klim > SS) klim = SS;
    gemm_body<1, true>(s_p + (size_t)bh * SS * SS, nullptr,
                       s_vt + (size_t)(b * NKV + kv) * HD * SS, nullptr,
                       nullptr, s_o + (size_t)b * SS * QC + h * HD,
                       klim, SS, SS, QC);
}

// ---------------- transpose / elementwise ----------------
// transpose: fp32 [R,C] -> fp16 [C,R]
__global__ void __launch_bounds__(256) k_t16(const float* __restrict__ in,
                                             f16* __restrict__ o, int R, int C) {
    __shared__ float t[32][33];
    int c0 = blockIdx.x * 32, r0 = blockIdx.y * 32;
    int tx = threadIdx.x & 31, ty = threadIdx.x >> 5;
#pragma unroll
    for (int i = 0; i < 4; i++)
        t[ty + i * 8][tx] = in[(size_t)(r0 + ty + i * 8) * C + c0 + tx];
    __syncthreads();
#pragma unroll
    for (int i = 0; i < 4; i++)
        o[(size_t)(c0 + ty + i * 8) * R + r0 + tx] = __float2half_rn(t[tx][ty + i * 8]);
}

// rmsnorm -> fp16
__global__ void __launch_bounds__(256) k_rms16(const float* __restrict__ x,
                                               const float* __restrict__ g,
                                               f16* __restrict__ o) {
    int row = blockIdx.x;
    const float* xr = x + (size_t)row * HH;
    float s = 0.0f;
    for (int i = threadIdx.x; i < HH; i += 256) { float v = xr[i]; s = fmaf(v, v, s); }
    __shared__ float red[256];
    red[threadIdx.x] = s;
    __syncthreads();
    for (int off = 128; off > 0; off >>= 1) {
        if (threadIdx.x < off) red[threadIdx.x] += red[threadIdx.x + off];
        __syncthreads();
    }
    float rstd = rsqrtf(red[0] * (1.0f / HH) + RMS_EPS);
    size_t base = (size_t)row * HH;
    for (int i = threadIdx.x; i < HH; i += 256)
        o[base + i] = __float2half_rn(xr[i] * rstd * (1.0f + g[i]));
}

// out = res + rmsnorm(y, g)  (fp32)
__global__ void __launch_bounds__(256) k_add_rms(const float* __restrict__ res,
                                                 const float* __restrict__ y,
                                                 const float* __restrict__ g,
                                                 float* __restrict__ out) {
    int row = blockIdx.x;
    const float* yr = y + (size_t)row * HH;
    float s = 0.0f;
    for (int i = threadIdx.x; i < HH; i += 256) { float v = yr[i]; s = fmaf(v, v, s); }
    __shared__ float red[256];
    red[threadIdx.x] = s;
    __syncthreads();
    for (int off = 128; off > 0; off >>= 1) {
        if (threadIdx.x < off) red[threadIdx.x] += red[threadIdx.x + off];
        __syncthreads();
    }
    float rstd = rsqrtf(red[0] * (1.0f / HH) + RMS_EPS);
    const float* rr = res + (size_t)row * HH;
    float* orow = out + (size_t)row * HH;
    for (int i = threadIdx.x; i < HH; i += 256)
        orow[i] = rr[i] + yr[i] * rstd * (1.0f + g[i]);
}

// RoPE on fp32 q/k -> fp16 hi/lo split buffers
__global__ void __launch_bounds__(256) k_rope_split() {
    int idx = blockIdx.x * 256 + threadIdx.x;            // < MROWS*12*128
    int j = idx & 127;
    int hd = (idx >> 7) % 12;
    int row = idx / (12 * 128);
    int pos = row & (SS - 1);
    float inv = __powf(10000.0f, -(float)(2 * j) * (1.0f / HD));
    float fr = (float)pos * inv;
    float sn, cs;
    sincosf(fr, &sn, &cs);
    const float* base;
    f16 *ohi, *olo;
    size_t off;
    if (hd < 8) {
        off = (size_t)row * QC + hd * HD;
        base = g_q + off; ohi = s_q_hi + off; olo = s_q_lo + off;
    } else {
        off = (size_t)row * KC + (hd - 8) * HD;
        base = g_k + off; ohi = s_k_hi + off; olo = s_k_lo + off;
    }
    float v0 = base[j], v1 = base[j + 128];
    split2h(v0 * cs - v1 * sn, ohi + j, olo + j);
    split2h(v1 * cs + v0 * sn, ohi + j + 128, olo + j + 128);
}

// V: fp32 [B,S,NKV,HD] -> fp16 transposed [B*NKV, HD, S]
__global__ void __launch_bounds__(256) k_vtrans() {
    __shared__ float t[32][33];
    int bkv = blockIdx.z;
    int b = bkv >> 2, kv = bkv & 3;
    int d0 = blockIdx.x * 32, s0 = blockIdx.y * 32;
    int tx = threadIdx.x & 31, ty = threadIdx.x >> 5;
#pragma unroll
    for (int i = 0; i < 4; i++)
        t[ty + i * 8][tx] = g_v[(size_t)(b * SS + s0 + ty + i * 8) * KC + kv * HD + d0 + tx];
    __syncthreads();
#pragma unroll
    for (int i = 0; i < 4; i++) {
        size_t o = (size_t)bkv * HD * SS + (size_t)(d0 + ty + i * 8) * SS + s0 + tx;
        s_vt[o] = __float2half_rn(t[tx][ty + i * 8]);
    }
}

// softmax (softcap + causal): only j <= qi read; zero-fill to 128-boundary; fp16 out
__global__ void __launch_bounds__(256) k_softmax() {
    int r = blockIdx.x;                 // bh*SS + qi
    int qi = r & (SS - 1);
    int nr = ((qi >> 7) + 1) << 7;
    const float* row = g_sc + (size_t)r * SS;
    int t = threadIdx.x;
    float vals[8];
    float mx = -1e30f;
    int it = 0;
    for (int j = t; j < nr; j += 256, it++) {
        float s = -1e30f;
        if (j <= qi) {
            s = row[j] * ATT_SCALE;
            s = SOFTCAP * tanhf(s * (1.0f / SOFTCAP));
            mx = fmaxf(mx, s);
        }
        vals[it] = s;
    }
    __shared__ float red[256];
    red[t] = mx;
    __syncthreads();
    for (int off = 128; off > 0; off >>= 1) {
        if (t < off) red[t] = fmaxf(red[t], red[t + off]);
        __syncthreads();
    }
    mx = red[0];
    __syncthreads();
    float sum = 0.0f;
    it = 0;
    for (int j = t; j < nr; j += 256, it++) {
        float e = (vals[it] > -1e29f) ? __expf(vals[it] - mx) : 0.0f;
        vals[it] = e;
        sum += e;
    }
    red[t] = sum;
    __syncthreads();
    for (int off = 128; off > 0; off >>= 1) {
        if (t < off) red[t] += red[t + off];
        __syncthreads();
    }
    float inv = 1.0f / red[0];
    size_t base = (size_t)r * SS;
    it = 0;
    for (int j = t; j < nr; j += 256, it++)
        s_p[base + j] = __float2half_rn(vals[it] * inv);
}

// GeGLU: act = gelu_tanh(gate) * up -> fp16
__global__ void __launch_bounds__(256) k_geglu() {
    size_t i = (size_t)blockIdx.x * 256 + threadIdx.x;
    float x = g_gate[i];
    float u = g_up[i];
    const float c0 = 0.7978845608028654f;
    float inner = c0 * fmaf(0.044715f * x * x, x, x);
    float act = 0.5f * x * (1.0f + tanhf(inner)) * u;
    s_a[i] = __float2half_rn(act);
}

// ---------------- launch ----------------
extern "C" void kernel_launch(void* const* d_in, const int* in_sizes, int n_in,
                              void* d_out, int out_size) {
    const float* x      = (const float*)d_in[0];
    // d_in[1] = mask (pure causal; applied analytically)
    const float* wq     = (const float*)d_in[2];
    const float* wk     = (const float*)d_in[3];
    const float* wv     = (const float*)d_in[4];
    const float* wo     = (const float*)d_in[5];
    const float* w_gate = (const float*)d_in[6];
    const float* w_up   = (const float*)d_in[7];
    const float* w_down = (const float*)d_in[8];
    const float* gin    = (const float*)d_in[9];
    const float* gpa    = (const float*)d_in[10];
    const float* gpf    = (const float*)d_in[11];
    const float* gpff   = (const float*)d_in[12];
    float* out = (float*)d_out;

    cudaFuncSetAttribute(k_gemm, cudaFuncAttributeMaxDynamicSharedMemorySize, SMEM_G1);
    cudaFuncSetAttribute(k_pv,   cudaFuncAttributeMaxDynamicSharedMemorySize, SMEM_G1);
    cudaFuncSetAttribute(k_qk,   cudaFuncAttributeMaxDynamicSharedMemorySize, SMEM_G3);

#define SYM(p, s) void* p; cudaGetSymbolAddress(&p, s)
    SYM(p_h, s_h);
    SYM(p_q, g_q);  SYM(p_k, g_k);  SYM(p_v, g_v);
    SYM(p_o, s_o);
    SYM(p_attn, g_attn); SYM(p_h2, g_h2); SYM(p_f, s_f);
    SYM(p_gate, g_gate); SYM(p_up, g_up); SYM(p_a, s_a);
    SYM(p_mlp, g_mlp);
    SYM(p_wq, w_qt); SYM(p_wk, w_kt); SYM(p_wv, w_vt); SYM(p_wo, w_ot);
    SYM(p_wg, w_gt); SYM(p_wu, w_ut); SYM(p_wd, w_dt);
#undef SYM

    // weight transposes (fp32 [K,N] -> fp16 [N,K])
    k_t16<<<dim3(QC / 32, HH / 32), 256>>>(wq, (f16*)p_wq, HH, QC);
    k_t16<<<dim3(KC / 32, HH / 32), 256>>>(wk, (f16*)p_wk, HH, KC);
    k_t16<<<dim3(KC / 32, HH / 32), 256>>>(wv, (f16*)p_wv, HH, KC);
    k_t16<<<dim3(HH / 32, QC / 32), 256>>>(wo, (f16*)p_wo, QC, HH);
    k_t16<<<dim3(FF / 32, HH / 32), 256>>>(w_gate, (f16*)p_wg, HH, FF);
    k_t16<<<dim3(FF / 32, HH / 32), 256>>>(w_up,   (f16*)p_wu, HH, FF);
    k_t16<<<dim3(HH / 32, FF / 32), 256>>>(w_down, (f16*)p_wd, FF, HH);

    // h = rmsnorm(x, g_in) -> fp16
    k_rms16<<<MROWS, 256>>>(x, gin, (f16*)p_h);

    // q/k/v projections (fp32 out)
    k_gemm<<<dim3(QC / 256, MROWS / 128), 512, SMEM_G1>>>(
        (f16*)p_h, (f16*)p_wq, (float*)p_q, HH, HH, HH, QC);
    k_gemm<<<dim3(KC / 256, MROWS / 128), 512, SMEM_G1>>>(
        (f16*)p_h, (f16*)p_wk, (float*)p_k, HH, HH, HH, KC);
    k_gemm<<<dim3(KC / 256, MROWS / 128), 512, SMEM_G1>>>(
        (f16*)p_h, (f16*)p_wv, (float*)p_v, HH, HH, HH, KC);

    // RoPE -> q/k fp16 hi/lo; V transpose -> fp16
    k_rope_split<<<(MROWS * 12 * 128) / 256, 256>>>();
    k_vtrans<<<dim3(HD / 32, SS / 32, BB * NKV), 256>>>();

    // scores = q @ k^T (3-pass, causal tiles only)
    k_qk<<<dim3(SS / 256, SS / 128, BB * NH), 512, SMEM_G3>>>();

    // softcap + causal + softmax -> p fp16
    k_softmax<<<BB * NH * SS, 256>>>();

    // o = p @ v (causal K-limit, fp16 out)
    k_pv<<<dim3(HD / 256, SS / 128, BB * NH), 512, SMEM_G1>>>();

    // attn_out = o @ wo
    k_gemm<<<dim3(HH / 256, MROWS / 128), 512, SMEM_G1>>>(
        (f16*)p_o, (f16*)p_wo, (float*)p_attn, QC, QC, QC, HH);

    // h2 = x + rmsnorm(attn); f = rmsnorm(h2) -> fp16
    k_add_rms<<<MROWS, 256>>>(x, (float*)p_attn, gpa, (float*)p_h2);
    k_rms16<<<MROWS, 256>>>((float*)p_h2, gpf, (f16*)p_f);

    // gate/up
    k_gemm<<<dim3(FF / 256, MROWS / 128), 512, SMEM_G1>>>(
        (f16*)p_f, (f16*)p_wg, (float*)p_gate, HH, HH, HH, FF);
    k_gemm<<<dim3(FF / 256, MROWS / 128), 512, SMEM_G1>>>(
        (f16*)p_f, (f16*)p_wu, (float*)p_up, HH, HH, HH, FF);

    // GeGLU -> fp16
    k_geglu<<<(int)(((size_t)MROWS * FF) / 256), 256>>>();

    // mlp = act @ w_down
    k_gemm<<<dim3(HH / 256, MROWS / 128), 512, SMEM_G1>>>(
        (f16*)p_a, (f16*)p_wd, (float*)p_mlp, FF, FF, FF, HH);

    // out = h2 + rmsnorm(mlp)
    k_add_rms<<<MROWS, 256>>>((float*)p_h2, (float*)p_mlp, gpff, out);
}